// round 12
// baseline (speedup 1.0000x reference)
#include <cuda_runtime.h>
#include <cuda_fp16.h>
#include <cstdint>

#define NN 50000
#define NG 64
#define DD 256
#define NE 800000
#define VOCAB 100000

#define WB  6250   // embed warp-blocks: NN/8 (exact: 6250*8 == 50000)
#define CB  3125   // edge blocks: NE/256
#define SB  196    // ceil(NN/256)
#define VB  12500  // emb-convert blocks: VOCAB/8
#define TB  32     // W-transpose blocks (16 per layer)
#define PG  296    // persistent gemm CTAs (2 per SM x 148)
#define NRT 391    // row tiles: ceil(NN/128)

// ---------------- scratch (device globals: no allocation allowed) -------------
__device__ __half g_EMBH[VOCAB * DD];  // fp16 embedding table (per-call convert)
__device__ __half g_W0T[DD * DD];      // W0 fp16, transposed [n][k]
__device__ __half g_W1T[DD * DD];      // W1 fp16, transposed [n][k]
__device__ __half g_XH[NN * DD];       // layer input fp16
__device__ __half g_HSH[NN * DD];      // h * dis (GEMM out, norm-folded), fp16
__device__ float  g_DIS[NN];           // deg^{-1/2}
__device__ int    g_DEG[NN];
__device__ int    g_ROWPTR[NN + 1];
__device__ int    g_CPOS[NN];
__device__ int    g_CSRC[NE];
__device__ int    g_GSTART[NG + 1];
__device__ unsigned long long g_STATE[SB];
__device__ int    g_TICKET;

// ---------------- prep: emb fp16 ∥ W transpose ∥ zero ∥ gstart ∥ zero-out ------
__global__ void __launch_bounds__(256) k_prep(const int* __restrict__ batch,
                                              const float* __restrict__ emb,
                                              const float* __restrict__ W0,
                                              const float* __restrict__ W1,
                                              float* __restrict__ out) {
    if (blockIdx.x < VB) {
        int row = blockIdx.x * 8 + (threadIdx.x >> 5);
        int lane = threadIdx.x & 31;
        const float4* src = (const float4*)emb + row * 64;
        float4 v0 = __ldg(src + 2 * lane);
        float4 v1 = __ldg(src + 2 * lane + 1);
        union { uint4 u; __half2 h2[4]; } pk;
        pk.h2[0] = __floats2half2_rn(v0.x, v0.y);
        pk.h2[1] = __floats2half2_rn(v0.z, v0.w);
        pk.h2[2] = __floats2half2_rn(v1.x, v1.y);
        pk.h2[3] = __floats2half2_rn(v1.z, v1.w);
        ((uint4*)g_EMBH)[row * 32 + lane] = pk.u;
        return;
    }
    int b = blockIdx.x - VB;
    int t = threadIdx.x;
    if (b < SB) {
        int n = b * 256 + t;
        if (n < NN) g_DEG[n] = 0;
        if (b == 0) {
            if (t < SB) g_STATE[t] = 0ull;
            if (t == 0) g_TICKET = 0;
        }
        if (b == 1 && t <= NG) {
            int lo = 0, hi = NN;
            while (lo < hi) {
                int mid = (lo + hi) >> 1;
                if (__ldg(batch + mid) < t) lo = mid + 1; else hi = mid;
            }
            g_GSTART[t] = lo;
        }
        if (b == 2) {
            for (int i = t; i < NG * DD; i += 256) out[i] = 0.f;
        }
    } else {
        // W transpose: fp32 [k][n] -> fp16 [n][k]
        int b2 = b - SB;
        const float* Ws = (b2 < 16) ? W0 : W1;
        __half* Wd = (b2 < 16) ? g_W0T : g_W1T;
        int kbase = (b2 & 15) * 16;
#pragma unroll
        for (int p = 0; p < 8; p++) {
            int k = kbase + 2 * p;
            float v0 = __ldg(Ws + k * DD + t);
            float v1 = __ldg(Ws + (k + 1) * DD + t);
            *(__half2*)&Wd[t * DD + k] = __floats2half2_rn(v0, v1);
        }
    }
}

// fused: embed (fp16 table gather) ∥ degree count -------------------------------
__global__ void __launch_bounds__(256) k_embed_count(const int* __restrict__ seq,
                                                     const int* __restrict__ edge) {
    if (blockIdx.x < WB) {
        int w = blockIdx.x * 8 + (threadIdx.x >> 5);
        int lane = threadIdx.x & 31;
        if (w >= NN) return;
        int tok = (lane < 16) ? seq[w * 16 + lane] : 0;
        const uint4* E = (const uint4*)g_EMBH;
        float acc[8];
#pragma unroll
        for (int q = 0; q < 8; q++) acc[q] = 0.f;
#pragma unroll
        for (int t = 0; t < 16; t++) {
            int tk = __shfl_sync(0xffffffffu, tok, t);
            uint4 v = __ldg(E + tk * 32 + lane);
            float2 f0 = __half22float2(*(__half2*)&v.x);
            float2 f1 = __half22float2(*(__half2*)&v.y);
            float2 f2 = __half22float2(*(__half2*)&v.z);
            float2 f3 = __half22float2(*(__half2*)&v.w);
            acc[0] += f0.x; acc[1] += f0.y;
            acc[2] += f1.x; acc[3] += f1.y;
            acc[4] += f2.x; acc[5] += f2.y;
            acc[6] += f3.x; acc[7] += f3.y;
        }
        union { uint4 u; __half2 h2[4]; } pk;
        pk.h2[0] = __floats2half2_rn(acc[0], acc[1]);
        pk.h2[1] = __floats2half2_rn(acc[2], acc[3]);
        pk.h2[2] = __floats2half2_rn(acc[4], acc[5]);
        pk.h2[3] = __floats2half2_rn(acc[6], acc[7]);
        ((uint4*)g_XH)[w * 32 + lane] = pk.u;
    } else {
        int e = (blockIdx.x - WB) * 256 + threadIdx.x;
        if (e < NE) atomicAdd(&g_DEG[edge[NE + e]], 1);
    }
}

// ---- single-pass decoupled-lookback exclusive scan (+ CPOS, DIS fused) -------
__device__ __forceinline__ int block_scan_incl(int v, int t) {
    __shared__ int ws[8];
    int x = v;
#pragma unroll
    for (int o = 1; o < 32; o <<= 1) {
        int y = __shfl_up_sync(0xffffffffu, x, o);
        if ((t & 31) >= o) x += y;
    }
    if ((t & 31) == 31) ws[t >> 5] = x;
    __syncthreads();
    if (t < 8) {
        int s = ws[t];
#pragma unroll
        for (int o = 1; o < 8; o <<= 1) {
            int y = __shfl_up_sync(0xffu, s, o);
            if (t >= o) s += y;
        }
        ws[t] = s;
    }
    __syncthreads();
    int offs = (t >= 32) ? ws[(t >> 5) - 1] : 0;
    return x + offs;
}

__global__ void __launch_bounds__(256) k_scan() {
    __shared__ int s_bid, s_total, s_prefix;
    int t = threadIdx.x;
    if (t == 0) s_bid = atomicAdd(&g_TICKET, 1);
    __syncthreads();
    int bid = s_bid;
    int i = bid * 256 + t;
    int deg = (i < NN) ? g_DEG[i] : 0;
    int incl = block_scan_incl(deg, t);
    if (t == 255) s_total = incl;
    __syncthreads();
    if (t == 0) {
        int total = s_total;
        if (bid == 0) {
            atomicExch(&g_STATE[0], (2ull << 32) | (unsigned)total);
            s_prefix = 0;
        } else {
            atomicExch(&g_STATE[bid], (1ull << 32) | (unsigned)total);
            int pref = 0;
            int p = bid - 1;
            while (p >= 0) {
                unsigned long long st;
                do { st = atomicAdd(&g_STATE[p], 0ull); } while ((st >> 32) == 0ull);
                pref += (int)(st & 0xffffffffull);
                if ((st >> 32) == 2ull) break;
                p--;
            }
            s_prefix = pref;
            atomicExch(&g_STATE[bid], (2ull << 32) | (unsigned)(pref + total));
        }
    }
    __syncthreads();
    int rp = s_prefix + incl - deg;
    if (i < NN) {
        g_ROWPTR[i] = rp;
        g_CPOS[i] = rp;
        g_DIS[i] = rsqrtf((float)deg + 1.0f);
    }
    if (i == 0) g_ROWPTR[NN] = NE;
}

// ---------- persistent FP16 GEMM: W resident in smem, A cp.async 3-stage ------
#define MMA_F16S(d, a0, a1, a2, a3, b0, b1)                                    \
    asm volatile(                                                              \
        "mma.sync.aligned.m16n8k16.row.col.f32.f16.f16.f32 "                   \
        "{%0,%1,%2,%3},{%4,%5,%6,%7},{%8,%9},{%0,%1,%2,%3};"                   \
        : "+f"(d[0]), "+f"(d[1]), "+f"(d[2]), "+f"(d[3])                       \
        : "r"(a0), "r"(a1), "r"(a2), "r"(a3), "r"(b0), "r"(b1))

#define LDSM_X4(r0, r1, r2, r3, addr)                                          \
    asm volatile("ldmatrix.sync.aligned.m8n8.x4.shared.b16 {%0,%1,%2,%3}, [%4];" \
                 : "=r"(r0), "=r"(r1), "=r"(r2), "=r"(r3) : "r"(addr))

#define CP16(saddr, gptr)                                                      \
    asm volatile("cp.async.ca.shared.global [%0], [%1], 16;"                   \
                 :: "r"(saddr), "l"(gptr))
#define CP_COMMIT() asm volatile("cp.async.commit_group;")

#define ASTR 40   // A smem row stride (halves)
#define WSTR 264  // W smem row stride (halves)

struct __align__(16) GemmPSmem {
    __half Ws[128 * WSTR];    // resident W column tile [n][k]
    __half As[3][128 * ASTR];
};

template <int FILL>
__global__ void __launch_bounds__(256, 2) k_gemm_p(const __half* __restrict__ WT,
                                                   const float* __restrict__ bias,
                                                   const int* __restrict__ edge) {
    __shared__ GemmPSmem sm;
    int cid = blockIdx.x;
    int bC = cid & 1;
    int crow = cid >> 1;
    int tid = threadIdx.x;
    int warp = tid >> 5, lane = tid & 31;
    int r = lane >> 2, c = lane & 3;
    int wm = (warp >> 2) * 64;
    int wn = (warp & 3) * 32;

    uint32_t wBase = (uint32_t)__cvta_generic_to_shared(sm.Ws);
    const __half* gW = WT + bC * 128 * DD;
#pragma unroll
    for (int i = 0; i < 16; i++) {
        int ch = tid + i * 256;
        int row = ch >> 5;
        int ko = (ch & 31) * 8;
        CP16(wBase + (row * WSTR + ko) * 2, gW + row * DD + ko);
    }
    CP_COMMIT();

    if (FILL) {
        const int per = (NE + PG - 1) / PG;
        int e0 = cid * per;
        int e1 = e0 + per; if (e1 > NE) e1 = NE;
        for (int e = e0 + tid; e < e1; e += 256) {
            int dst = edge[NE + e];
            int p = atomicAdd(&g_CPOS[dst], 1);
            g_CSRC[p] = edge[e];
        }
    }

    asm volatile("cp.async.wait_group 0;");
    __syncthreads();

    int lrow = lane & 7;
    int sel = lane >> 3;
    int aRow = lrow + ((sel & 1) << 3);
    int aKof = (sel & 2) ? 8 : 0;
    int bRow = lrow + ((sel >> 1) << 3);
    int bKof = (sel & 1) ? 8 : 0;

    uint32_t sA0 = (uint32_t)__cvta_generic_to_shared(&sm.As[0][0]);
    const uint32_t STG_B = 128 * ASTR * 2;
    int mrow = tid >> 1;
    int kh = (tid & 1) * 16;
    uint32_t dOffA = (mrow * ASTR + kh) * 2;

    for (int bR = crow; bR < NRT; bR += 148) {
        int rowA = bR * 128 + mrow;
        int rowAc = rowA < NN ? rowA : NN - 1;
        const __half* gA = g_XH + rowAc * DD + kh;

        float acc[4][4][4];
#pragma unroll
        for (int i = 0; i < 4; i++)
#pragma unroll
            for (int j = 0; j < 4; j++)
#pragma unroll
                for (int q = 0; q < 4; q++) acc[i][j][q] = 0.f;

#pragma unroll
        for (int pt = 0; pt < 2; pt++) {
            uint32_t dA = sA0 + pt * STG_B + dOffA;
            CP16(dA, gA + pt * 32); CP16(dA + 16, gA + pt * 32 + 8);
            CP_COMMIT();
        }

#pragma unroll 1
        for (int it = 0; it < 8; it++) {
            if (it < 7) asm volatile("cp.async.wait_group 1;");
            else        asm volatile("cp.async.wait_group 0;");
            __syncthreads();

            if (it + 2 < 8) {
                int st = (it + 2) % 3;
                uint32_t dA = sA0 + st * STG_B + dOffA;
                CP16(dA, gA + (it + 2) * 32); CP16(dA + 16, gA + (it + 2) * 32 + 8);
                CP_COMMIT();
            }

            uint32_t aBase = sA0 + (it % 3) * STG_B;
#pragma unroll
            for (int kc = 0; kc < 2; kc++) {
                int k0 = it * 32 + kc * 16;
                uint32_t a[4][4], bb[2][4];
#pragma unroll
                for (int ti = 0; ti < 4; ti++) {
                    uint32_t addr = aBase + ((wm + ti * 16 + aRow) * ASTR + kc * 16 + aKof) * 2;
                    LDSM_X4(a[ti][0], a[ti][1], a[ti][2], a[ti][3], addr);
                }
#pragma unroll
                for (int tjp = 0; tjp < 2; tjp++) {
                    uint32_t addr = wBase + ((wn + tjp * 16 + bRow) * WSTR + k0 + bKof) * 2;
                    LDSM_X4(bb[tjp][0], bb[tjp][1], bb[tjp][2], bb[tjp][3], addr);
                }
#pragma unroll
                for (int ti = 0; ti < 4; ti++) {
#pragma unroll
                    for (int tjp = 0; tjp < 2; tjp++) {
                        MMA_F16S(acc[ti][2 * tjp], a[ti][0], a[ti][1], a[ti][2], a[ti][3],
                                 bb[tjp][0], bb[tjp][1]);
                        MMA_F16S(acc[ti][2 * tjp + 1], a[ti][0], a[ti][1], a[ti][2], a[ti][3],
                                 bb[tjp][2], bb[tjp][3]);
                    }
                }
            }
        }
        __syncthreads();

#pragma unroll
        for (int ti = 0; ti < 4; ti++) {
            int row0 = bR * 128 + wm + ti * 16 + r;
            int row1 = row0 + 8;
            float dis0 = (row0 < NN) ? g_DIS[row0] : 0.f;
            float dis1 = (row1 < NN) ? g_DIS[row1] : 0.f;
#pragma unroll
            for (int tj = 0; tj < 4; tj++) {
                int col = bC * 128 + wn + tj * 8 + 2 * c;
                float bx = __ldg(bias + col), by = __ldg(bias + col + 1);
                if (row0 < NN) {
                    __half2 h = __floats2half2_rn((acc[ti][tj][0] + bx) * dis0,
                                                  (acc[ti][tj][1] + by) * dis0);
                    *(__half2*)(g_HSH + row0 * DD + col) = h;
                }
                if (row1 < NN) {
                    __half2 h = __floats2half2_rn((acc[ti][tj][2] + bx) * dis1,
                                                  (acc[ti][tj][3] + by) * dis1);
                    *(__half2*)(g_HSH + row1 * DD + col) = h;
                }
            }
        }
    }
}

// ---------------- aggregation: warp per node, fp16 rows (512B) ----------------
// LAYER1: writes relu(dis*(sum+HS)) to g_XH (fp16).
// LAYER2: pools relu(dis*(sum+HS)) directly into out via smem bins + gmem atomics.
__device__ __forceinline__ int graph_of(int n) {
    int lo = 0, hi = NG - 1;
    while (lo < hi) {
        int mid = (lo + hi + 1) >> 1;
        if (g_GSTART[mid] <= n) lo = mid; else hi = mid - 1;
    }
    return lo;
}

template <int LAYER1>
__global__ void __launch_bounds__(256) k_agg(float* __restrict__ out) {
    __shared__ float bins[8][DD];
    __shared__ int s_g0, s_maxbin;
    int tid = threadIdx.x;
    int w = blockIdx.x * 8 + (tid >> 5);
    int lane = tid & 31;

    if (!LAYER1) {
        for (int i = tid; i < 8 * DD; i += 256) ((float*)bins)[i] = 0.f;
        if (tid == 0) { s_g0 = graph_of(blockIdx.x * 8); s_maxbin = 0; }
        __syncthreads();
    }

    float o[8];
    bool valid = (w < NN);
    if (valid) {
        int s = g_ROWPTR[w], e = g_ROWPTR[w + 1];
        const uint4* HS = (const uint4*)g_HSH;
        float acc[8];
#pragma unroll
        for (int q = 0; q < 8; q++) acc[q] = 0.f;
        for (int base = s; base < e; base += 32) {
            int cnt = e - base; if (cnt > 32) cnt = 32;
            int mysrc = (lane < cnt) ? g_CSRC[base + lane] : 0;
#pragma unroll 4
            for (int i = 0; i < cnt; i++) {
                int src = __shfl_sync(0xffffffffu, mysrc, i);
                uint4 v = __ldg(HS + src * 32 + lane);
                float2 f0 = __half22float2(*(__half2*)&v.x);
                float2 f1 = __half22float2(*(__half2*)&v.y);
                float2 f2 = __half22float2(*(__half2*)&v.z);
                float2 f3 = __half22float2(*(__half2*)&v.w);
                acc[0] += f0.x; acc[1] += f0.y;
                acc[2] += f1.x; acc[3] += f1.y;
                acc[4] += f2.x; acc[5] += f2.y;
                acc[6] += f3.x; acc[7] += f3.y;
            }
        }
        uint4 sv = __ldg(HS + w * 32 + lane);
        float2 s0 = __half22float2(*(__half2*)&sv.x);
        float2 s1 = __half22float2(*(__half2*)&sv.y);
        float2 s2 = __half22float2(*(__half2*)&sv.z);
        float2 s3 = __half22float2(*(__half2*)&sv.w);
        float dis = g_DIS[w];
        o[0] = fmaxf(dis * (acc[0] + s0.x), 0.f);
        o[1] = fmaxf(dis * (acc[1] + s0.y), 0.f);
        o[2] = fmaxf(dis * (acc[2] + s1.x), 0.f);
        o[3] = fmaxf(dis * (acc[3] + s1.y), 0.f);
        o[4] = fmaxf(dis * (acc[4] + s2.x), 0.f);
        o[5] = fmaxf(dis * (acc[5] + s2.y), 0.f);
        o[6] = fmaxf(dis * (acc[6] + s3.x), 0.f);
        o[7] = fmaxf(dis * (acc[7] + s3.y), 0.f);
    }

    if (LAYER1) {
        if (valid) {
            union { uint4 u; __half2 h2[4]; } pk;
            pk.h2[0] = __floats2half2_rn(o[0], o[1]);
            pk.h2[1] = __floats2half2_rn(o[2], o[3]);
            pk.h2[2] = __floats2half2_rn(o[4], o[5]);
            pk.h2[3] = __floats2half2_rn(o[6], o[7]);
            ((uint4*)g_XH)[w * 32 + lane] = pk.u;
        }
    } else {
        if (valid) {
            int bin = graph_of(w) - s_g0;   // 8 consecutive nodes span <= 8 graphs
            if (lane == 0) atomicMax(&s_maxbin, bin);
#pragma unroll
            for (int j = 0; j < 8; j++)
                atomicAdd(&bins[bin][lane * 8 + j], o[j]);
        }
        __syncthreads();
        int mb = s_maxbin;
        for (int b = 0; b <= mb; b++)
            atomicAdd(&out[(s_g0 + b) * DD + tid], bins[b][tid]);
    }
}

// ---------------- launch ------------------------------------------------------

extern "C" void kernel_launch(void* const* d_in, const int* in_sizes, int n_in,
                              void* d_out, int out_size) {
    const int *seq = nullptr, *edge = nullptr, *batch = nullptr;
    const float *emb = nullptr, *W0 = nullptr, *b0 = nullptr, *W1 = nullptr, *b1 = nullptr;
    for (int i = 0; i < n_in; i++) {
        int s = in_sizes[i];
        if (s == NN * 16)            seq  = (const int*)d_in[i];
        else if (s == 2 * NE)        edge = (const int*)d_in[i];
        else if (s == NN)            batch = (const int*)d_in[i];
        else if (s == VOCAB * DD)    emb  = (const float*)d_in[i];
        else if (s == DD * DD) { if (!W0) W0 = (const float*)d_in[i]; else W1 = (const float*)d_in[i]; }
        else if (s == DD)      { if (!b0) b0 = (const float*)d_in[i]; else b1 = (const float*)d_in[i]; }
    }
    float* out = (float*)d_out;

    __half* w0t; cudaGetSymbolAddress((void**)&w0t, g_W0T);
    __half* w1t; cudaGetSymbolAddress((void**)&w1t, g_W1T);

    k_prep<<<VB + SB + TB, 256>>>(batch, emb, W0, W1, out);
    k_embed_count<<<WB + CB, 256>>>(seq, edge);
    k_scan<<<SB, 256>>>();

    // layer 1: persistent GEMM with W0 resident + CSR fill inside
    k_gemm_p<1><<<PG, 256>>>(w0t, b0, edge);
    k_agg<1><<<WB, 256>>>(nullptr);
    // layer 2: persistent GEMM with W1 resident, then fused agg+pool
    k_gemm_p<0><<<PG, 256>>>(w1t, b1, nullptr);
    k_agg<0><<<WB, 256>>>(out);
}

// round 13
// speedup vs baseline: 1.0873x; 1.0873x over previous
#include <cuda_runtime.h>
#include <cuda_fp16.h>
#include <cstdint>

#define NN 50000
#define NG 64
#define DD 256
#define NE 800000
#define VOCAB 100000

#define WB  6250   // embed warp-blocks: NN/8
#define CB  3125   // edge blocks: NE/256
#define SB  196    // ceil(NN/256)
#define VB  12500  // emb-convert blocks: VOCAB/8
#define TB  32     // W-transpose blocks (16 per layer)
#define PG  296    // persistent gemm CTAs (2 per SM x 148)
#define NRT 391    // row tiles: ceil(NN/128)

// ---------------- scratch (device globals: no allocation allowed) -------------
__device__ __half g_EMBH[VOCAB * DD];  // fp16 embedding table (per-call convert)
__device__ __half g_W0T[DD * DD];      // W0 fp16, transposed [n][k]
__device__ __half g_W1T[DD * DD];      // W1 fp16, transposed [n][k]
__device__ __half g_XH[NN * DD];       // layer input fp16
__device__ __half g_HSH[NN * DD];      // h * dis (GEMM out, norm-folded), fp16
__device__ __half g_UH[NN * DD];       // layer2 final node feats (fp16)
__device__ float  g_DIS[NN];           // deg^{-1/2}
__device__ int    g_DEG[NN];           // zero-inited at load; re-zeroed each call in agg1 tail
__device__ int    g_ROWPTR[NN + 1];
__device__ int    g_CPOS[NN];
__device__ int    g_CSRC[NE];
__device__ int    g_GSTART[NG + 1];
__device__ float  g_PART[8 * NG * DD];
__device__ unsigned long long g_STATE[SB];
__device__ int    g_TICKET;

// ------ prep: emb fp16 ∥ W transpose ∥ scan-state ∥ gstart ∥ degree COUNT ------
__global__ void __launch_bounds__(256) k_prep(const int* __restrict__ batch,
                                              const float* __restrict__ emb,
                                              const float* __restrict__ W0,
                                              const float* __restrict__ W1,
                                              const int* __restrict__ edge) {
    if (blockIdx.x < VB) {
        int row = blockIdx.x * 8 + (threadIdx.x >> 5);
        int lane = threadIdx.x & 31;
        const float4* src = (const float4*)emb + row * 64;
        float4 v0 = __ldg(src + 2 * lane);
        float4 v1 = __ldg(src + 2 * lane + 1);
        union { uint4 u; __half2 h2[4]; } pk;
        pk.h2[0] = __floats2half2_rn(v0.x, v0.y);
        pk.h2[1] = __floats2half2_rn(v0.z, v0.w);
        pk.h2[2] = __floats2half2_rn(v1.x, v1.y);
        pk.h2[3] = __floats2half2_rn(v1.z, v1.w);
        ((uint4*)g_EMBH)[row * 32 + lane] = pk.u;
        return;
    }
    int b = blockIdx.x - VB;
    int t = threadIdx.x;
    if (b == 0) {
        if (t < SB) g_STATE[t] = 0ull;
        if (t == 0) g_TICKET = 0;
    } else if (b == 1) {
        if (t <= NG) {
            int lo = 0, hi = NN;
            while (lo < hi) {
                int mid = (lo + hi) >> 1;
                if (__ldg(batch + mid) < t) lo = mid + 1; else hi = mid;
            }
            g_GSTART[t] = lo;
        }
    } else if (b < 2 + TB) {
        // W transpose: fp32 [k][n] -> fp16 [n][k]
        int b2 = b - 2;
        const float* Ws = (b2 < 16) ? W0 : W1;
        __half* Wd = (b2 < 16) ? g_W0T : g_W1T;
        int kbase = (b2 & 15) * 16;
#pragma unroll
        for (int p = 0; p < 8; p++) {
            int k = kbase + 2 * p;
            float v0 = __ldg(Ws + k * DD + t);
            float v1 = __ldg(Ws + (k + 1) * DD + t);
            *(__half2*)&Wd[t * DD + k] = __floats2half2_rn(v0, v1);
        }
    } else {
        // degree count (g_DEG pre-zeroed: load-time init or previous call's agg1 tail)
        int e = (b - 2 - TB) * 256 + t;
        if (e < NE) atomicAdd(&g_DEG[edge[NE + e]], 1);
    }
}

// ---- scan helpers -------------------------------------------------------------
__device__ __forceinline__ int block_scan_incl(int v, int t) {
    __shared__ int ws[8];
    int x = v;
#pragma unroll
    for (int o = 1; o < 32; o <<= 1) {
        int y = __shfl_up_sync(0xffffffffu, x, o);
        if ((t & 31) >= o) x += y;
    }
    if ((t & 31) == 31) ws[t >> 5] = x;
    __syncthreads();
    if (t < 8) {
        int s = ws[t];
#pragma unroll
        for (int o = 1; o < 8; o <<= 1) {
            int y = __shfl_up_sync(0xffu, s, o);
            if (t >= o) s += y;
        }
        ws[t] = s;
    }
    __syncthreads();
    int offs = (t >= 32) ? ws[(t >> 5) - 1] : 0;
    return x + offs;
}

// fused: embed (fp16 table gather, blocks [0,WB)) ∥ decoupled-lookback scan ------
__global__ void __launch_bounds__(256) k_embed_scan(const int* __restrict__ seq) {
    if (blockIdx.x < WB) {
        int w = blockIdx.x * 8 + (threadIdx.x >> 5);
        int lane = threadIdx.x & 31;
        if (w >= NN) return;
        int tok = (lane < 16) ? seq[w * 16 + lane] : 0;
        const uint4* E = (const uint4*)g_EMBH;
        float acc[8];
#pragma unroll
        for (int q = 0; q < 8; q++) acc[q] = 0.f;
#pragma unroll
        for (int t = 0; t < 16; t++) {
            int tk = __shfl_sync(0xffffffffu, tok, t);
            uint4 v = __ldg(E + tk * 32 + lane);
            float2 f0 = __half22float2(*(__half2*)&v.x);
            float2 f1 = __half22float2(*(__half2*)&v.y);
            float2 f2 = __half22float2(*(__half2*)&v.z);
            float2 f3 = __half22float2(*(__half2*)&v.w);
            acc[0] += f0.x; acc[1] += f0.y;
            acc[2] += f1.x; acc[3] += f1.y;
            acc[4] += f2.x; acc[5] += f2.y;
            acc[6] += f3.x; acc[7] += f3.y;
        }
        union { uint4 u; __half2 h2[4]; } pk;
        pk.h2[0] = __floats2half2_rn(acc[0], acc[1]);
        pk.h2[1] = __floats2half2_rn(acc[2], acc[3]);
        pk.h2[2] = __floats2half2_rn(acc[4], acc[5]);
        pk.h2[3] = __floats2half2_rn(acc[6], acc[7]);
        ((uint4*)g_XH)[w * 32 + lane] = pk.u;
        return;
    }
    // --- scan role (196 blocks, ticket-ordered decoupled lookback) ---
    __shared__ int s_bid, s_total, s_prefix;
    int t = threadIdx.x;
    if (t == 0) s_bid = atomicAdd(&g_TICKET, 1);
    __syncthreads();
    int bid = s_bid;
    int i = bid * 256 + t;
    int deg = (i < NN) ? g_DEG[i] : 0;
    int incl = block_scan_incl(deg, t);
    if (t == 255) s_total = incl;
    __syncthreads();
    if (t == 0) {
        int total = s_total;
        if (bid == 0) {
            atomicExch(&g_STATE[0], (2ull << 32) | (unsigned)total);
            s_prefix = 0;
        } else {
            atomicExch(&g_STATE[bid], (1ull << 32) | (unsigned)total);
            int pref = 0;
            int p = bid - 1;
            while (p >= 0) {
                unsigned long long st;
                do { st = atomicAdd(&g_STATE[p], 0ull); } while ((st >> 32) == 0ull);
                pref += (int)(st & 0xffffffffull);
                if ((st >> 32) == 2ull) break;
                p--;
            }
            s_prefix = pref;
            atomicExch(&g_STATE[bid], (2ull << 32) | (unsigned)(pref + total));
        }
    }
    __syncthreads();
    int rp = s_prefix + incl - deg;
    if (i < NN) {
        g_ROWPTR[i] = rp;
        g_CPOS[i] = rp;
        g_DIS[i] = rsqrtf((float)deg + 1.0f);
    }
    if (i == 0) g_ROWPTR[NN] = NE;
}

// ---------- persistent FP16 GEMM: W resident in smem, A cp.async 3-stage ------
#define MMA_F16S(d, a0, a1, a2, a3, b0, b1)                                    \
    asm volatile(                                                              \
        "mma.sync.aligned.m16n8k16.row.col.f32.f16.f16.f32 "                   \
        "{%0,%1,%2,%3},{%4,%5,%6,%7},{%8,%9},{%0,%1,%2,%3};"                   \
        : "+f"(d[0]), "+f"(d[1]), "+f"(d[2]), "+f"(d[3])                       \
        : "r"(a0), "r"(a1), "r"(a2), "r"(a3), "r"(b0), "r"(b1))

#define LDSM_X4(r0, r1, r2, r3, addr)                                          \
    asm volatile("ldmatrix.sync.aligned.m8n8.x4.shared.b16 {%0,%1,%2,%3}, [%4];" \
                 : "=r"(r0), "=r"(r1), "=r"(r2), "=r"(r3) : "r"(addr))

#define CP16(saddr, gptr)                                                      \
    asm volatile("cp.async.ca.shared.global [%0], [%1], 16;"                   \
                 :: "r"(saddr), "l"(gptr))
#define CP_COMMIT() asm volatile("cp.async.commit_group;")

#define ASTR 40   // A smem row stride (halves)
#define WSTR 264  // W smem row stride (halves)

struct __align__(16) GemmPSmem {
    __half Ws[128 * WSTR];
    __half As[3][128 * ASTR];
};

template <int FILL>
__global__ void __launch_bounds__(256, 2) k_gemm_p(const __half* __restrict__ WT,
                                                   const float* __restrict__ bias,
                                                   const int* __restrict__ edge) {
    __shared__ GemmPSmem sm;
    int cid = blockIdx.x;
    int bC = cid & 1;
    int crow = cid >> 1;
    int tid = threadIdx.x;
    int warp = tid >> 5, lane = tid & 31;
    int r = lane >> 2, c = lane & 3;
    int wm = (warp >> 2) * 64;
    int wn = (warp & 3) * 32;

    uint32_t wBase = (uint32_t)__cvta_generic_to_shared(sm.Ws);
    const __half* gW = WT + bC * 128 * DD;
#pragma unroll
    for (int i = 0; i < 16; i++) {
        int ch = tid + i * 256;
        int row = ch >> 5;
        int ko = (ch & 31) * 8;
        CP16(wBase + (row * WSTR + ko) * 2, gW + row * DD + ko);
    }
    CP_COMMIT();

    if (FILL) {
        const int per = (NE + PG - 1) / PG;
        int e0 = cid * per;
        int e1 = e0 + per; if (e1 > NE) e1 = NE;
        for (int e = e0 + tid; e < e1; e += 256) {
            int dst = edge[NE + e];
            int p = atomicAdd(&g_CPOS[dst], 1);
            g_CSRC[p] = edge[e];
        }
    }

    asm volatile("cp.async.wait_group 0;");
    __syncthreads();

    int lrow = lane & 7;
    int sel = lane >> 3;
    int aRow = lrow + ((sel & 1) << 3);
    int aKof = (sel & 2) ? 8 : 0;
    int bRow = lrow + ((sel >> 1) << 3);
    int bKof = (sel & 1) ? 8 : 0;

    uint32_t sA0 = (uint32_t)__cvta_generic_to_shared(&sm.As[0][0]);
    const uint32_t STG_B = 128 * ASTR * 2;
    int mrow = tid >> 1;
    int kh = (tid & 1) * 16;
    uint32_t dOffA = (mrow * ASTR + kh) * 2;

    for (int bR = crow; bR < NRT; bR += 148) {
        int rowA = bR * 128 + mrow;
        int rowAc = rowA < NN ? rowA : NN - 1;
        const __half* gA = g_XH + rowAc * DD + kh;

        float acc[4][4][4];
#pragma unroll
        for (int i = 0; i < 4; i++)
#pragma unroll
            for (int j = 0; j < 4; j++)
#pragma unroll
                for (int q = 0; q < 4; q++) acc[i][j][q] = 0.f;

#pragma unroll
        for (int pt = 0; pt < 2; pt++) {
            uint32_t dA = sA0 + pt * STG_B + dOffA;
            CP16(dA, gA + pt * 32); CP16(dA + 16, gA + pt * 32 + 8);
            CP_COMMIT();
        }

#pragma unroll 1
        for (int it = 0; it < 8; it++) {
            if (it < 7) asm volatile("cp.async.wait_group 1;");
            else        asm volatile("cp.async.wait_group 0;");
            __syncthreads();

            if (it + 2 < 8) {
                int st = (it + 2) % 3;
                uint32_t dA = sA0 + st * STG_B + dOffA;
                CP16(dA, gA + (it + 2) * 32); CP16(dA + 16, gA + (it + 2) * 32 + 8);
                CP_COMMIT();
            }

            uint32_t aBase = sA0 + (it % 3) * STG_B;
#pragma unroll
            for (int kc = 0; kc < 2; kc++) {
                int k0 = it * 32 + kc * 16;
                uint32_t a[4][4], bb[2][4];
#pragma unroll
                for (int ti = 0; ti < 4; ti++) {
                    uint32_t addr = aBase + ((wm + ti * 16 + aRow) * ASTR + kc * 16 + aKof) * 2;
                    LDSM_X4(a[ti][0], a[ti][1], a[ti][2], a[ti][3], addr);
                }
#pragma unroll
                for (int tjp = 0; tjp < 2; tjp++) {
                    uint32_t addr = wBase + ((wn + tjp * 16 + bRow) * WSTR + k0 + bKof) * 2;
                    LDSM_X4(bb[tjp][0], bb[tjp][1], bb[tjp][2], bb[tjp][3], addr);
                }
#pragma unroll
                for (int ti = 0; ti < 4; ti++) {
#pragma unroll
                    for (int tjp = 0; tjp < 2; tjp++) {
                        MMA_F16S(acc[ti][2 * tjp], a[ti][0], a[ti][1], a[ti][2], a[ti][3],
                                 bb[tjp][0], bb[tjp][1]);
                        MMA_F16S(acc[ti][2 * tjp + 1], a[ti][0], a[ti][1], a[ti][2], a[ti][3],
                                 bb[tjp][2], bb[tjp][3]);
                    }
                }
            }
        }
        __syncthreads();

#pragma unroll
        for (int ti = 0; ti < 4; ti++) {
            int row0 = bR * 128 + wm + ti * 16 + r;
            int row1 = row0 + 8;
            float dis0 = (row0 < NN) ? g_DIS[row0] : 0.f;
            float dis1 = (row1 < NN) ? g_DIS[row1] : 0.f;
#pragma unroll
            for (int tj = 0; tj < 4; tj++) {
                int col = bC * 128 + wn + tj * 8 + 2 * c;
                float bx = __ldg(bias + col), by = __ldg(bias + col + 1);
                if (row0 < NN) {
                    __half2 h = __floats2half2_rn((acc[ti][tj][0] + bx) * dis0,
                                                  (acc[ti][tj][1] + by) * dis0);
                    *(__half2*)(g_HSH + row0 * DD + col) = h;
                }
                if (row1 < NN) {
                    __half2 h = __floats2half2_rn((acc[ti][tj][2] + bx) * dis1,
                                                  (acc[ti][tj][3] + by) * dis1);
                    *(__half2*)(g_HSH + row1 * DD + col) = h;
                }
            }
        }
    }
}

// ---------------- aggregation: warp per node, fp16 rows (512B) ----------------
// LAYER1: writes g_XH fp16 (+ tail blocks zero DEG for next call).
// LAYER2: writes g_UH fp16.
template <int LAYER1>
__global__ void __launch_bounds__(256) k_agg() {
    if (LAYER1 && blockIdx.x >= WB) {
        int n = (blockIdx.x - WB) * 256 + threadIdx.x;
        if (n < NN) g_DEG[n] = 0;   // DEG's last use was the scan; reset for next call
        return;
    }
    int w = blockIdx.x * 8 + (threadIdx.x >> 5);
    int lane = threadIdx.x & 31;
    if (w >= NN) return;
    int s = g_ROWPTR[w], e = g_ROWPTR[w + 1];
    const uint4* HS = (const uint4*)g_HSH;
    float acc[8];
#pragma unroll
    for (int q = 0; q < 8; q++) acc[q] = 0.f;

    for (int base = s; base < e; base += 32) {
        int cnt = e - base; if (cnt > 32) cnt = 32;
        int mysrc = (lane < cnt) ? g_CSRC[base + lane] : 0;
#pragma unroll 4
        for (int i = 0; i < cnt; i++) {
            int src = __shfl_sync(0xffffffffu, mysrc, i);
            uint4 v = __ldg(HS + src * 32 + lane);
            float2 f0 = __half22float2(*(__half2*)&v.x);
            float2 f1 = __half22float2(*(__half2*)&v.y);
            float2 f2 = __half22float2(*(__half2*)&v.z);
            float2 f3 = __half22float2(*(__half2*)&v.w);
            acc[0] += f0.x; acc[1] += f0.y;
            acc[2] += f1.x; acc[3] += f1.y;
            acc[4] += f2.x; acc[5] += f2.y;
            acc[6] += f3.x; acc[7] += f3.y;
        }
    }
    uint4 sv = __ldg(HS + w * 32 + lane);
    float2 s0 = __half22float2(*(__half2*)&sv.x);
    float2 s1 = __half22float2(*(__half2*)&sv.y);
    float2 s2 = __half22float2(*(__half2*)&sv.z);
    float2 s3 = __half22float2(*(__half2*)&sv.w);
    float dis = g_DIS[w];
    float o[8];
    o[0] = fmaxf(dis * (acc[0] + s0.x), 0.f);
    o[1] = fmaxf(dis * (acc[1] + s0.y), 0.f);
    o[2] = fmaxf(dis * (acc[2] + s1.x), 0.f);
    o[3] = fmaxf(dis * (acc[3] + s1.y), 0.f);
    o[4] = fmaxf(dis * (acc[4] + s2.x), 0.f);
    o[5] = fmaxf(dis * (acc[5] + s2.y), 0.f);
    o[6] = fmaxf(dis * (acc[6] + s3.x), 0.f);
    o[7] = fmaxf(dis * (acc[7] + s3.y), 0.f);
    union { uint4 u; __half2 h2[4]; } pk;
    pk.h2[0] = __floats2half2_rn(o[0], o[1]);
    pk.h2[1] = __floats2half2_rn(o[2], o[3]);
    pk.h2[2] = __floats2half2_rn(o[4], o[5]);
    pk.h2[3] = __floats2half2_rn(o[6], o[7]);
    if (LAYER1) ((uint4*)g_XH)[w * 32 + lane] = pk.u;
    else        ((uint4*)g_UH)[w * 32 + lane] = pk.u;
}

// pool pass 1: 8 node-chunks per graph -> partial sums (fp16 U, fp32 accum)
__global__ void k_pool1() {
    int g = blockIdx.x, ch = blockIdx.y;
    int t = threadIdx.x;   // 64 threads, 4 cols each
    int s = g_GSTART[g], e = g_GSTART[g + 1];
    int len = e - s;
    int c0 = s + (int)(((long long)len * ch) >> 3);
    int c1 = s + (int)(((long long)len * (ch + 1)) >> 3);
    const uint2* U2 = (const uint2*)g_UH;   // row = 64 uint2 (256 halves)
    float4 acc = make_float4(0.f, 0.f, 0.f, 0.f);
    for (int n = c0; n < c1; n++) {
        uint2 v = __ldg(U2 + n * 64 + t);
        float2 f0 = __half22float2(*(__half2*)&v.x);
        float2 f1 = __half22float2(*(__half2*)&v.y);
        acc.x += f0.x; acc.y += f0.y; acc.z += f1.x; acc.w += f1.y;
    }
    ((float4*)g_PART)[(ch * NG + g) * 64 + t] = acc;
}

__global__ void k_pool2(float* __restrict__ out) {
    int g = blockIdx.x;
    int t = threadIdx.x;   // 64
    const float4* P4 = (const float4*)g_PART;
    float4 acc = make_float4(0.f, 0.f, 0.f, 0.f);
#pragma unroll
    for (int ch = 0; ch < 8; ch++) {
        float4 v = P4[(ch * NG + g) * 64 + t];
        acc.x += v.x; acc.y += v.y; acc.z += v.z; acc.w += v.w;
    }
    ((float4*)out)[g * 64 + t] = acc;
}

// ---------------- launch ------------------------------------------------------

extern "C" void kernel_launch(void* const* d_in, const int* in_sizes, int n_in,
                              void* d_out, int out_size) {
    const int *seq = nullptr, *edge = nullptr, *batch = nullptr;
    const float *emb = nullptr, *W0 = nullptr, *b0 = nullptr, *W1 = nullptr, *b1 = nullptr;
    for (int i = 0; i < n_in; i++) {
        int s = in_sizes[i];
        if (s == NN * 16)            seq  = (const int*)d_in[i];
        else if (s == 2 * NE)        edge = (const int*)d_in[i];
        else if (s == NN)            batch = (const int*)d_in[i];
        else if (s == VOCAB * DD)    emb  = (const float*)d_in[i];
        else if (s == DD * DD) { if (!W0) W0 = (const float*)d_in[i]; else W1 = (const float*)d_in[i]; }
        else if (s == DD)      { if (!b0) b0 = (const float*)d_in[i]; else b1 = (const float*)d_in[i]; }
    }
    float* out = (float*)d_out;

    __half* w0t; cudaGetSymbolAddress((void**)&w0t, g_W0T);
    __half* w1t; cudaGetSymbolAddress((void**)&w1t, g_W1T);

    // prep: emb convert ∥ W transpose ∥ scan-state reset ∥ gstart ∥ degree count
    k_prep<<<VB + 2 + TB + CB, 256>>>(batch, emb, W0, W1, edge);
    // embed gather ∥ prefix scan (scan hides under embed)
    k_embed_scan<<<WB + SB, 256>>>(seq);

    // layer 1: persistent GEMM with W0 resident + CSR fill inside
    k_gemm_p<1><<<PG, 256>>>(w0t, b0, edge);
    k_agg<1><<<WB + SB, 256>>>();   // + DEG re-zero tail for next call
    // layer 2
    k_gemm_p<0><<<PG, 256>>>(w1t, b1, nullptr);
    k_agg<0><<<WB, 256>>>();
    // pool
    dim3 pg(NG, 8);
    k_pool1<<<pg, 64>>>();
    k_pool2<<<NG, 64>>>(out);
}

// round 14
// speedup vs baseline: 1.1146x; 1.0251x over previous
#include <cuda_runtime.h>
#include <cuda_fp16.h>
#include <cstdint>

#define NN 50000
#define NG 64
#define DD 256
#define NE 800000
#define VOCAB 100000

#define WB  6250   // embed warp-blocks: NN/8
#define CB  3125   // edge blocks: NE/256
#define SB  196    // ceil(NN/256)
#define VB  12500  // emb-convert blocks: VOCAB/8
#define TB  32     // W-transpose blocks (16 per layer)
#define PG  296    // persistent gemm CTAs (2 per SM x 148)
#define NRT 391    // row tiles: ceil(NN/128)

// ---------------- scratch (device globals: no allocation allowed) -------------
__device__ __half g_EMBH[VOCAB * DD];  // fp16 embedding table (per-call convert)
__device__ __half g_W0T[DD * DD];      // W0 fp16, transposed [n][k]
__device__ __half g_W1T[DD * DD];      // W1 fp16, transposed [n][k]
__device__ __half g_XH[NN * DD];       // layer input fp16
__device__ __half g_HSH[NN * DD];      // h * dis (GEMM out, norm-folded), fp16
__device__ __half g_UH[NN * DD];       // layer2 final node feats (fp16)
__device__ float  g_DIS[NN];           // deg^{-1/2}
__device__ int    g_DEG[NN];           // zero-inited at load; re-zeroed in agg1 tail
__device__ int    g_ROWPTR[NN + 1];
__device__ int    g_CPOS[NN];
__device__ int    g_CSRC[NE];
__device__ int    g_GSTART[NG + 1];
__device__ float  g_PART[8 * NG * DD];
__device__ unsigned long long g_STATE[SB];
__device__ int    g_TICKET;

// ------ prep: emb fp16 ∥ W transpose ∥ scan-state ∥ gstart ∥ degree COUNT ------
__global__ void __launch_bounds__(256) k_prep(const int* __restrict__ batch,
                                              const float* __restrict__ emb,
                                              const float* __restrict__ W0,
                                              const float* __restrict__ W1,
                                              const int* __restrict__ edge) {
    if (blockIdx.x < VB) {
        int row = blockIdx.x * 8 + (threadIdx.x >> 5);
        int lane = threadIdx.x & 31;
        const float4* src = (const float4*)emb + row * 64;
        float4 v0 = __ldg(src + 2 * lane);
        float4 v1 = __ldg(src + 2 * lane + 1);
        union { uint4 u; __half2 h2[4]; } pk;
        pk.h2[0] = __floats2half2_rn(v0.x, v0.y);
        pk.h2[1] = __floats2half2_rn(v0.z, v0.w);
        pk.h2[2] = __floats2half2_rn(v1.x, v1.y);
        pk.h2[3] = __floats2half2_rn(v1.z, v1.w);
        ((uint4*)g_EMBH)[row * 32 + lane] = pk.u;
        return;
    }
    int b = blockIdx.x - VB;
    int t = threadIdx.x;
    if (b == 0) {
        if (t < SB) g_STATE[t] = 0ull;
        if (t == 0) g_TICKET = 0;
    } else if (b == 1) {
        if (t <= NG) {
            int lo = 0, hi = NN;
            while (lo < hi) {
                int mid = (lo + hi) >> 1;
                if (__ldg(batch + mid) < t) lo = mid + 1; else hi = mid;
            }
            g_GSTART[t] = lo;
        }
    } else if (b < 2 + TB) {
        int b2 = b - 2;
        const float* Ws = (b2 < 16) ? W0 : W1;
        __half* Wd = (b2 < 16) ? g_W0T : g_W1T;
        int kbase = (b2 & 15) * 16;
#pragma unroll
        for (int p = 0; p < 8; p++) {
            int k = kbase + 2 * p;
            float v0 = __ldg(Ws + k * DD + t);
            float v1 = __ldg(Ws + (k + 1) * DD + t);
            *(__half2*)&Wd[t * DD + k] = __floats2half2_rn(v0, v1);
        }
    } else {
        int e = (b - 2 - TB) * 256 + t;
        if (e < NE) atomicAdd(&g_DEG[edge[NE + e]], 1);
    }
}

// ---- scan helpers -------------------------------------------------------------
__device__ __forceinline__ int block_scan_incl(int v, int t) {
    __shared__ int ws[8];
    int x = v;
#pragma unroll
    for (int o = 1; o < 32; o <<= 1) {
        int y = __shfl_up_sync(0xffffffffu, x, o);
        if ((t & 31) >= o) x += y;
    }
    if ((t & 31) == 31) ws[t >> 5] = x;
    __syncthreads();
    if (t < 8) {
        int s = ws[t];
#pragma unroll
        for (int o = 1; o < 8; o <<= 1) {
            int y = __shfl_up_sync(0xffu, s, o);
            if (t >= o) s += y;
        }
        ws[t] = s;
    }
    __syncthreads();
    int offs = (t >= 32) ? ws[(t >> 5) - 1] : 0;
    return x + offs;
}

// fused: embed (fp16 gather, HADD2 accum) ∥ decoupled-lookback scan --------------
__global__ void __launch_bounds__(256) k_embed_scan(const int* __restrict__ seq) {
    if (blockIdx.x < WB) {
        int w = blockIdx.x * 8 + (threadIdx.x >> 5);
        int lane = threadIdx.x & 31;
        if (w >= NN) return;
        int tok = (lane < 16) ? seq[w * 16 + lane] : 0;
        const uint4* E = (const uint4*)g_EMBH;
        float acc[8];
#pragma unroll
        for (int q = 0; q < 8; q++) acc[q] = 0.f;
        const __half2 hz = __float2half2_rn(0.f);
#pragma unroll
        for (int g8 = 0; g8 < 2; g8++) {
            __half2 ah0 = hz, ah1 = hz, ah2 = hz, ah3 = hz;
#pragma unroll
            for (int t = 0; t < 8; t++) {
                int tk = __shfl_sync(0xffffffffu, tok, g8 * 8 + t);
                uint4 v = __ldg(E + tk * 32 + lane);
                ah0 = __hadd2(ah0, *(__half2*)&v.x);
                ah1 = __hadd2(ah1, *(__half2*)&v.y);
                ah2 = __hadd2(ah2, *(__half2*)&v.z);
                ah3 = __hadd2(ah3, *(__half2*)&v.w);
            }
            float2 f0 = __half22float2(ah0), f1 = __half22float2(ah1);
            float2 f2 = __half22float2(ah2), f3 = __half22float2(ah3);
            acc[0] += f0.x; acc[1] += f0.y; acc[2] += f1.x; acc[3] += f1.y;
            acc[4] += f2.x; acc[5] += f2.y; acc[6] += f3.x; acc[7] += f3.y;
        }
        union { uint4 u; __half2 h2[4]; } pk;
        pk.h2[0] = __floats2half2_rn(acc[0], acc[1]);
        pk.h2[1] = __floats2half2_rn(acc[2], acc[3]);
        pk.h2[2] = __floats2half2_rn(acc[4], acc[5]);
        pk.h2[3] = __floats2half2_rn(acc[6], acc[7]);
        ((uint4*)g_XH)[w * 32 + lane] = pk.u;
        return;
    }
    // --- scan role (196 blocks, ticket-ordered decoupled lookback) ---
    __shared__ int s_bid, s_total, s_prefix;
    int t = threadIdx.x;
    if (t == 0) s_bid = atomicAdd(&g_TICKET, 1);
    __syncthreads();
    int bid = s_bid;
    int i = bid * 256 + t;
    int deg = (i < NN) ? g_DEG[i] : 0;
    int incl = block_scan_incl(deg, t);
    if (t == 255) s_total = incl;
    __syncthreads();
    if (t == 0) {
        int total = s_total;
        if (bid == 0) {
            atomicExch(&g_STATE[0], (2ull << 32) | (unsigned)total);
            s_prefix = 0;
        } else {
            atomicExch(&g_STATE[bid], (1ull << 32) | (unsigned)total);
            int pref = 0;
            int p = bid - 1;
            while (p >= 0) {
                unsigned long long st;
                do { st = atomicAdd(&g_STATE[p], 0ull); } while ((st >> 32) == 0ull);
                pref += (int)(st & 0xffffffffull);
                if ((st >> 32) == 2ull) break;
                p--;
            }
            s_prefix = pref;
            atomicExch(&g_STATE[bid], (2ull << 32) | (unsigned)(pref + total));
        }
    }
    __syncthreads();
    int rp = s_prefix + incl - deg;
    if (i < NN) {
        g_ROWPTR[i] = rp;
        g_CPOS[i] = rp;
        g_DIS[i] = rsqrtf((float)deg + 1.0f);
    }
    if (i == 0) g_ROWPTR[NN] = NE;
}

// ---------- persistent FP16 GEMM: W resident in smem, A cp.async 3-stage ------
#define MMA_F16S(d, a0, a1, a2, a3, b0, b1)                                    \
    asm volatile(                                                              \
        "mma.sync.aligned.m16n8k16.row.col.f32.f16.f16.f32 "                   \
        "{%0,%1,%2,%3},{%4,%5,%6,%7},{%8,%9},{%0,%1,%2,%3};"                   \
        : "+f"(d[0]), "+f"(d[1]), "+f"(d[2]), "+f"(d[3])                       \
        : "r"(a0), "r"(a1), "r"(a2), "r"(a3), "r"(b0), "r"(b1))

#define LDSM_X4(r0, r1, r2, r3, addr)                                          \
    asm volatile("ldmatrix.sync.aligned.m8n8.x4.shared.b16 {%0,%1,%2,%3}, [%4];" \
                 : "=r"(r0), "=r"(r1), "=r"(r2), "=r"(r3) : "r"(addr))

#define CP16(saddr, gptr)                                                      \
    asm volatile("cp.async.ca.shared.global [%0], [%1], 16;"                   \
                 :: "r"(saddr), "l"(gptr))
#define CP_COMMIT() asm volatile("cp.async.commit_group;")

#define ASTR 40   // A smem row stride (halves)
#define WSTR 264  // W smem row stride (halves)

struct __align__(16) GemmPSmem {
    __half Ws[128 * WSTR];
    __half As[3][128 * ASTR];
};

template <int FILL>
__global__ void __launch_bounds__(256, 2) k_gemm_p(const __half* __restrict__ WT,
                                                   const float* __restrict__ bias,
                                                   const int* __restrict__ edge) {
    __shared__ GemmPSmem sm;
    int cid = blockIdx.x;
    int bC = cid & 1;
    int crow = cid >> 1;
    int tid = threadIdx.x;
    int warp = tid >> 5, lane = tid & 31;
    int r = lane >> 2, c = lane & 3;
    int wm = (warp >> 2) * 64;
    int wn = (warp & 3) * 32;

    uint32_t wBase = (uint32_t)__cvta_generic_to_shared(sm.Ws);
    const __half* gW = WT + bC * 128 * DD;
#pragma unroll
    for (int i = 0; i < 16; i++) {
        int ch = tid + i * 256;
        int row = ch >> 5;
        int ko = (ch & 31) * 8;
        CP16(wBase + (row * WSTR + ko) * 2, gW + row * DD + ko);
    }
    CP_COMMIT();

    if (FILL) {
        const int per = (NE + PG - 1) / PG;
        int e0 = cid * per;
        int e1 = e0 + per; if (e1 > NE) e1 = NE;
        for (int e = e0 + tid; e < e1; e += 256) {
            int dst = edge[NE + e];
            int p = atomicAdd(&g_CPOS[dst], 1);
            g_CSRC[p] = edge[e];
        }
    }

    asm volatile("cp.async.wait_group 0;");
    __syncthreads();

    int lrow = lane & 7;
    int sel = lane >> 3;
    int aRow = lrow + ((sel & 1) << 3);
    int aKof = (sel & 2) ? 8 : 0;
    int bRow = lrow + ((sel >> 1) << 3);
    int bKof = (sel & 1) ? 8 : 0;

    uint32_t sA0 = (uint32_t)__cvta_generic_to_shared(&sm.As[0][0]);
    const uint32_t STG_B = 128 * ASTR * 2;
    int mrow = tid >> 1;
    int kh = (tid & 1) * 16;
    uint32_t dOffA = (mrow * ASTR + kh) * 2;

    for (int bR = crow; bR < NRT; bR += 148) {
        int rowA = bR * 128 + mrow;
        int rowAc = rowA < NN ? rowA : NN - 1;
        const __half* gA = g_XH + rowAc * DD + kh;

        float acc[4][4][4];
#pragma unroll
        for (int i = 0; i < 4; i++)
#pragma unroll
            for (int j = 0; j < 4; j++)
#pragma unroll
                for (int q = 0; q < 4; q++) acc[i][j][q] = 0.f;

#pragma unroll
        for (int pt = 0; pt < 2; pt++) {
            uint32_t dA = sA0 + pt * STG_B + dOffA;
            CP16(dA, gA + pt * 32); CP16(dA + 16, gA + pt * 32 + 8);
            CP_COMMIT();
        }

#pragma unroll 1
        for (int it = 0; it < 8; it++) {
            if (it < 7) asm volatile("cp.async.wait_group 1;");
            else        asm volatile("cp.async.wait_group 0;");
            __syncthreads();

            if (it + 2 < 8) {
                int st = (it + 2) % 3;
                uint32_t dA = sA0 + st * STG_B + dOffA;
                CP16(dA, gA + (it + 2) * 32); CP16(dA + 16, gA + (it + 2) * 32 + 8);
                CP_COMMIT();
            }

            uint32_t aBase = sA0 + (it % 3) * STG_B;
#pragma unroll
            for (int kc = 0; kc < 2; kc++) {
                int k0 = it * 32 + kc * 16;
                uint32_t a[4][4], bb[2][4];
#pragma unroll
                for (int ti = 0; ti < 4; ti++) {
                    uint32_t addr = aBase + ((wm + ti * 16 + aRow) * ASTR + kc * 16 + aKof) * 2;
                    LDSM_X4(a[ti][0], a[ti][1], a[ti][2], a[ti][3], addr);
                }
#pragma unroll
                for (int tjp = 0; tjp < 2; tjp++) {
                    uint32_t addr = wBase + ((wn + tjp * 16 + bRow) * WSTR + k0 + bKof) * 2;
                    LDSM_X4(bb[tjp][0], bb[tjp][1], bb[tjp][2], bb[tjp][3], addr);
                }
#pragma unroll
                for (int ti = 0; ti < 4; ti++) {
#pragma unroll
                    for (int tjp = 0; tjp < 2; tjp++) {
                        MMA_F16S(acc[ti][2 * tjp], a[ti][0], a[ti][1], a[ti][2], a[ti][3],
                                 bb[tjp][0], bb[tjp][1]);
                        MMA_F16S(acc[ti][2 * tjp + 1], a[ti][0], a[ti][1], a[ti][2], a[ti][3],
                                 bb[tjp][2], bb[tjp][3]);
                    }
                }
            }
        }
        __syncthreads();

#pragma unroll
        for (int ti = 0; ti < 4; ti++) {
            int row0 = bR * 128 + wm + ti * 16 + r;
            int row1 = row0 + 8;
            float dis0 = (row0 < NN) ? g_DIS[row0] : 0.f;
            float dis1 = (row1 < NN) ? g_DIS[row1] : 0.f;
#pragma unroll
            for (int tj = 0; tj < 4; tj++) {
                int col = bC * 128 + wn + tj * 8 + 2 * c;
                float bx = __ldg(bias + col), by = __ldg(bias + col + 1);
                if (row0 < NN) {
                    __half2 h = __floats2half2_rn((acc[ti][tj][0] + bx) * dis0,
                                                  (acc[ti][tj][1] + by) * dis0);
                    *(__half2*)(g_HSH + row0 * DD + col) = h;
                }
                if (row1 < NN) {
                    __half2 h = __floats2half2_rn((acc[ti][tj][2] + bx) * dis1,
                                                  (acc[ti][tj][3] + by) * dis1);
                    *(__half2*)(g_HSH + row1 * DD + col) = h;
                }
            }
        }
    }
}

// ------- aggregation: warp/node, HADD2 accumulation, fp32 flush every 8 --------
template <int LAYER1>
__global__ void __launch_bounds__(256) k_agg() {
    if (LAYER1 && blockIdx.x >= WB) {
        int n = (blockIdx.x - WB) * 256 + threadIdx.x;
        if (n < NN) g_DEG[n] = 0;   // reset for next call
        return;
    }
    int w = blockIdx.x * 8 + (threadIdx.x >> 5);
    int lane = threadIdx.x & 31;
    if (w >= NN) return;
    int s = g_ROWPTR[w], e = g_ROWPTR[w + 1];
    const uint4* HS = (const uint4*)g_HSH;
    const __half2 hz = __float2half2_rn(0.f);
    float acc[8];
#pragma unroll
    for (int q = 0; q < 8; q++) acc[q] = 0.f;

    for (int base = s; base < e; base += 32) {
        int cnt = e - base; if (cnt > 32) cnt = 32;
        int mysrc = (lane < cnt) ? g_CSRC[base + lane] : 0;
        for (int i0 = 0; i0 < cnt; i0 += 8) {
            int iend = i0 + 8; if (iend > cnt) iend = cnt;
            __half2 ah0 = hz, ah1 = hz, ah2 = hz, ah3 = hz;
#pragma unroll 4
            for (int i = i0; i < iend; i++) {
                int src = __shfl_sync(0xffffffffu, mysrc, i);
                uint4 v = __ldg(HS + src * 32 + lane);
                ah0 = __hadd2(ah0, *(__half2*)&v.x);
                ah1 = __hadd2(ah1, *(__half2*)&v.y);
                ah2 = __hadd2(ah2, *(__half2*)&v.z);
                ah3 = __hadd2(ah3, *(__half2*)&v.w);
            }
            float2 f0 = __half22float2(ah0), f1 = __half22float2(ah1);
            float2 f2 = __half22float2(ah2), f3 = __half22float2(ah3);
            acc[0] += f0.x; acc[1] += f0.y; acc[2] += f1.x; acc[3] += f1.y;
            acc[4] += f2.x; acc[5] += f2.y; acc[6] += f3.x; acc[7] += f3.y;
        }
    }
    uint4 sv = __ldg(HS + w * 32 + lane);
    float2 s0 = __half22float2(*(__half2*)&sv.x);
    float2 s1 = __half22float2(*(__half2*)&sv.y);
    float2 s2 = __half22float2(*(__half2*)&sv.z);
    float2 s3 = __half22float2(*(__half2*)&sv.w);
    float dis = g_DIS[w];
    float o[8];
    o[0] = fmaxf(dis * (acc[0] + s0.x), 0.f);
    o[1] = fmaxf(dis * (acc[1] + s0.y), 0.f);
    o[2] = fmaxf(dis * (acc[2] + s1.x), 0.f);
    o[3] = fmaxf(dis * (acc[3] + s1.y), 0.f);
    o[4] = fmaxf(dis * (acc[4] + s2.x), 0.f);
    o[5] = fmaxf(dis * (acc[5] + s2.y), 0.f);
    o[6] = fmaxf(dis * (acc[6] + s3.x), 0.f);
    o[7] = fmaxf(dis * (acc[7] + s3.y), 0.f);
    union { uint4 u; __half2 h2[4]; } pk;
    pk.h2[0] = __floats2half2_rn(o[0], o[1]);
    pk.h2[1] = __floats2half2_rn(o[2], o[3]);
    pk.h2[2] = __floats2half2_rn(o[4], o[5]);
    pk.h2[3] = __floats2half2_rn(o[6], o[7]);
    if (LAYER1) ((uint4*)g_XH)[w * 32 + lane] = pk.u;
    else        ((uint4*)g_UH)[w * 32 + lane] = pk.u;
}

// pool pass 1: 8 node-chunks per graph -> partial sums (fp16 U, fp32 accum)
__global__ void k_pool1() {
    int g = blockIdx.x, ch = blockIdx.y;
    int t = threadIdx.x;
    int s = g_GSTART[g], e = g_GSTART[g + 1];
    int len = e - s;
    int c0 = s + (int)(((long long)len * ch) >> 3);
    int c1 = s + (int)(((long long)len * (ch + 1)) >> 3);
    const uint2* U2 = (const uint2*)g_UH;
    float4 acc = make_float4(0.f, 0.f, 0.f, 0.f);
    for (int n = c0; n < c1; n++) {
        uint2 v = __ldg(U2 + n * 64 + t);
        float2 f0 = __half22float2(*(__half2*)&v.x);
        float2 f1 = __half22float2(*(__half2*)&v.y);
        acc.x += f0.x; acc.y += f0.y; acc.z += f1.x; acc.w += f1.y;
    }
    ((float4*)g_PART)[(ch * NG + g) * 64 + t] = acc;
}

__global__ void k_pool2(float* __restrict__ out) {
    int g = blockIdx.x;
    int t = threadIdx.x;
    const float4* P4 = (const float4*)g_PART;
    float4 acc = make_float4(0.f, 0.f, 0.f, 0.f);
#pragma unroll
    for (int ch = 0; ch < 8; ch++) {
        float4 v = P4[(ch * NG + g) * 64 + t];
        acc.x += v.x; acc.y += v.y; acc.z += v.z; acc.w += v.w;
    }
    ((float4*)out)[g * 64 + t] = acc;
}

// ---------------- launch ------------------------------------------------------

extern "C" void kernel_launch(void* const* d_in, const int* in_sizes, int n_in,
                              void* d_out, int out_size) {
    const int *seq = nullptr, *edge = nullptr, *batch = nullptr;
    const float *emb = nullptr, *W0 = nullptr, *b0 = nullptr, *W1 = nullptr, *b1 = nullptr;
    for (int i = 0; i < n_in; i++) {
        int s = in_sizes[i];
        if (s == NN * 16)            seq  = (const int*)d_in[i];
        else if (s == 2 * NE)        edge = (const int*)d_in[i];
        else if (s == NN)            batch = (const int*)d_in[i];
        else if (s == VOCAB * DD)    emb  = (const float*)d_in[i];
        else if (s == DD * DD) { if (!W0) W0 = (const float*)d_in[i]; else W1 = (const float*)d_in[i]; }
        else if (s == DD)      { if (!b0) b0 = (const float*)d_in[i]; else b1 = (const float*)d_in[i]; }
    }
    float* out = (float*)d_out;

    __half* w0t; cudaGetSymbolAddress((void**)&w0t, g_W0T);
    __half* w1t; cudaGetSymbolAddress((void**)&w1t, g_W1T);

    k_prep<<<VB + 2 + TB + CB, 256>>>(batch, emb, W0, W1, edge);
    k_embed_scan<<<WB + SB, 256>>>(seq);

    // layer 1: persistent GEMM with W0 resident + CSR fill inside
    k_gemm_p<1><<<PG, 256>>>(w0t, b0, edge);
    k_agg<1><<<WB + SB, 256>>>();
    // layer 2
    k_gemm_p<0><<<PG, 256>>>(w1t, b1, nullptr);
    k_agg<0><<<WB, 256>>>();
    // pool
    dim3 pg(NG, 8);
    k_pool1<<<pg, 64>>>();
    k_pool2<<<NG, 64>>>(out);
}

// round 15
// speedup vs baseline: 1.1452x; 1.0275x over previous
#include <cuda_runtime.h>
#include <cuda_fp16.h>
#include <cstdint>

#define NN 50000
#define NG 64
#define DD 256
#define NE 800000
#define VOCAB 100000

#define WB  6250   // embed warp-blocks: NN/8
#define CB  3125   // edge blocks: NE/256
#define SB  196    // ceil(NN/256)
#define VB  12500  // emb-convert blocks: VOCAB/8
#define TB  32     // W-transpose blocks (16 per layer)
#define PG  296    // persistent gemm CTAs (2 per SM x 148)
#define NRT 391    // row tiles: ceil(NN/128)

// ---------------- scratch (device globals: no allocation allowed) -------------
__device__ __half g_EMBH[VOCAB * DD];  // fp16 embedding table (per-call convert)
__device__ __half g_W0T[DD * DD];      // W0 fp16, transposed [n][k]
__device__ __half g_W1T[DD * DD];      // W1 fp16, transposed [n][k]
__device__ __half g_XH[NN * DD];       // layer input fp16
__device__ __half g_HSH[NN * DD];      // h * dis (GEMM out, norm-folded), fp16
__device__ __half g_UH[NN * DD];       // layer2 final node feats (fp16)
__device__ float  g_DIS[NN];           // deg^{-1/2}
__device__ int    g_DEG[NN];           // zero-inited at load; re-zeroed in agg1 tail
__device__ int    g_ROWPTR[NN + 1];
__device__ int    g_CPOS[NN];
__device__ int    g_CSRC[NE];
__device__ int    g_GSTART[NG + 1];
__device__ float  g_PART[8 * NG * DD];
__device__ unsigned long long g_STATE[SB];
__device__ int    g_TICKET;

// ------ prep: emb fp16 ∥ W transpose ∥ scan-state ∥ gstart ∥ degree COUNT ------
__global__ void __launch_bounds__(256) k_prep(const int* __restrict__ batch,
                                              const float* __restrict__ emb,
                                              const float* __restrict__ W0,
                                              const float* __restrict__ W1,
                                              const int* __restrict__ edge) {
    if (blockIdx.x < VB) {
        int row = blockIdx.x * 8 + (threadIdx.x >> 5);
        int lane = threadIdx.x & 31;
        const float4* src = (const float4*)emb + row * 64;
        float4 v0 = __ldg(src + 2 * lane);
        float4 v1 = __ldg(src + 2 * lane + 1);
        union { uint4 u; __half2 h2[4]; } pk;
        pk.h2[0] = __floats2half2_rn(v0.x, v0.y);
        pk.h2[1] = __floats2half2_rn(v0.z, v0.w);
        pk.h2[2] = __floats2half2_rn(v1.x, v1.y);
        pk.h2[3] = __floats2half2_rn(v1.z, v1.w);
        ((uint4*)g_EMBH)[row * 32 + lane] = pk.u;
        return;
    }
    int b = blockIdx.x - VB;
    int t = threadIdx.x;
    if (b == 0) {
        if (t < SB) g_STATE[t] = 0ull;
        if (t == 0) g_TICKET = 0;
    } else if (b == 1) {
        if (t <= NG) {
            int lo = 0, hi = NN;
            while (lo < hi) {
                int mid = (lo + hi) >> 1;
                if (__ldg(batch + mid) < t) lo = mid + 1; else hi = mid;
            }
            g_GSTART[t] = lo;
        }
    } else if (b < 2 + TB) {
        int b2 = b - 2;
        const float* Ws = (b2 < 16) ? W0 : W1;
        __half* Wd = (b2 < 16) ? g_W0T : g_W1T;
        int kbase = (b2 & 15) * 16;
#pragma unroll
        for (int p = 0; p < 8; p++) {
            int k = kbase + 2 * p;
            float v0 = __ldg(Ws + k * DD + t);
            float v1 = __ldg(Ws + (k + 1) * DD + t);
            *(__half2*)&Wd[t * DD + k] = __floats2half2_rn(v0, v1);
        }
    } else {
        int e = (b - 2 - TB) * 256 + t;
        if (e < NE) atomicAdd(&g_DEG[edge[NE + e]], 1);
    }
}

// ---- scan helpers -------------------------------------------------------------
__device__ __forceinline__ int block_scan_incl(int v, int t) {
    __shared__ int ws[8];
    int x = v;
#pragma unroll
    for (int o = 1; o < 32; o <<= 1) {
        int y = __shfl_up_sync(0xffffffffu, x, o);
        if ((t & 31) >= o) x += y;
    }
    if ((t & 31) == 31) ws[t >> 5] = x;
    __syncthreads();
    if (t < 8) {
        int s = ws[t];
#pragma unroll
        for (int o = 1; o < 8; o <<= 1) {
            int y = __shfl_up_sync(0xffu, s, o);
            if (t >= o) s += y;
        }
        ws[t] = s;
    }
    __syncthreads();
    int offs = (t >= 32) ? ws[(t >> 5) - 1] : 0;
    return x + offs;
}

// fused: embed (fp16 gather, HADD2 accum) ∥ decoupled-lookback scan --------------
__global__ void __launch_bounds__(256) k_embed_scan(const int* __restrict__ seq) {
    if (blockIdx.x < WB) {
        int w = blockIdx.x * 8 + (threadIdx.x >> 5);
        int lane = threadIdx.x & 31;
        if (w >= NN) return;
        int tok = (lane < 16) ? seq[w * 16 + lane] : 0;
        const uint4* E = (const uint4*)g_EMBH;
        float acc[8];
#pragma unroll
        for (int q = 0; q < 8; q++) acc[q] = 0.f;
        const __half2 hz = __float2half2_rn(0.f);
#pragma unroll
        for (int g8 = 0; g8 < 2; g8++) {
            __half2 ah0 = hz, ah1 = hz, ah2 = hz, ah3 = hz;
#pragma unroll
            for (int t = 0; t < 8; t++) {
                int tk = __shfl_sync(0xffffffffu, tok, g8 * 8 + t);
                uint4 v = __ldg(E + tk * 32 + lane);
                ah0 = __hadd2(ah0, *(__half2*)&v.x);
                ah1 = __hadd2(ah1, *(__half2*)&v.y);
                ah2 = __hadd2(ah2, *(__half2*)&v.z);
                ah3 = __hadd2(ah3, *(__half2*)&v.w);
            }
            float2 f0 = __half22float2(ah0), f1 = __half22float2(ah1);
            float2 f2 = __half22float2(ah2), f3 = __half22float2(ah3);
            acc[0] += f0.x; acc[1] += f0.y; acc[2] += f1.x; acc[3] += f1.y;
            acc[4] += f2.x; acc[5] += f2.y; acc[6] += f3.x; acc[7] += f3.y;
        }
        union { uint4 u; __half2 h2[4]; } pk;
        pk.h2[0] = __floats2half2_rn(acc[0], acc[1]);
        pk.h2[1] = __floats2half2_rn(acc[2], acc[3]);
        pk.h2[2] = __floats2half2_rn(acc[4], acc[5]);
        pk.h2[3] = __floats2half2_rn(acc[6], acc[7]);
        ((uint4*)g_XH)[w * 32 + lane] = pk.u;
        return;
    }
    // --- scan role (196 blocks, ticket-ordered decoupled lookback) ---
    __shared__ int s_bid, s_total, s_prefix;
    int t = threadIdx.x;
    if (t == 0) s_bid = atomicAdd(&g_TICKET, 1);
    __syncthreads();
    int bid = s_bid;
    int i = bid * 256 + t;
    int deg = (i < NN) ? g_DEG[i] : 0;
    int incl = block_scan_incl(deg, t);
    if (t == 255) s_total = incl;
    __syncthreads();
    if (t == 0) {
        int total = s_total;
        if (bid == 0) {
            atomicExch(&g_STATE[0], (2ull << 32) | (unsigned)total);
            s_prefix = 0;
        } else {
            atomicExch(&g_STATE[bid], (1ull << 32) | (unsigned)total);
            int pref = 0;
            int p = bid - 1;
            while (p >= 0) {
                unsigned long long st;
                do { st = atomicAdd(&g_STATE[p], 0ull); } while ((st >> 32) == 0ull);
                pref += (int)(st & 0xffffffffull);
                if ((st >> 32) == 2ull) break;
                p--;
            }
            s_prefix = pref;
            atomicExch(&g_STATE[bid], (2ull << 32) | (unsigned)(pref + total));
        }
    }
    __syncthreads();
    int rp = s_prefix + incl - deg;
    if (i < NN) {
        g_ROWPTR[i] = rp;
        g_CPOS[i] = rp;
        g_DIS[i] = rsqrtf((float)deg + 1.0f);
    }
    if (i == 0) g_ROWPTR[NN] = NE;
}

// ---------- persistent FP16 GEMM: W resident in smem, A cp.async 3-stage ------
#define MMA_F16S(d, a0, a1, a2, a3, b0, b1)                                    \
    asm volatile(                                                              \
        "mma.sync.aligned.m16n8k16.row.col.f32.f16.f16.f32 "                   \
        "{%0,%1,%2,%3},{%4,%5,%6,%7},{%8,%9},{%0,%1,%2,%3};"                   \
        : "+f"(d[0]), "+f"(d[1]), "+f"(d[2]), "+f"(d[3])                       \
        : "r"(a0), "r"(a1), "r"(a2), "r"(a3), "r"(b0), "r"(b1))

#define LDSM_X4(r0, r1, r2, r3, addr)                                          \
    asm volatile("ldmatrix.sync.aligned.m8n8.x4.shared.b16 {%0,%1,%2,%3}, [%4];" \
                 : "=r"(r0), "=r"(r1), "=r"(r2), "=r"(r3) : "r"(addr))

#define CP16(saddr, gptr)                                                      \
    asm volatile("cp.async.ca.shared.global [%0], [%1], 16;"                   \
                 :: "r"(saddr), "l"(gptr))
#define CP_COMMIT() asm volatile("cp.async.commit_group;")

#define ASTR 40   // A smem row stride (halves)
#define WSTR 264  // W smem row stride (halves)

struct __align__(16) GemmPSmem {
    __half Ws[128 * WSTR];
    __half As[3][128 * ASTR];
};

template <int FILL>
__global__ void __launch_bounds__(256, 2) k_gemm_p(const __half* __restrict__ WT,
                                                   const float* __restrict__ bias,
                                                   const int* __restrict__ edge) {
    __shared__ GemmPSmem sm;
    int cid = blockIdx.x;
    int bC = cid & 1;
    int crow = cid >> 1;
    int tid = threadIdx.x;
    int warp = tid >> 5, lane = tid & 31;
    int r = lane >> 2, c = lane & 3;
    int wm = (warp >> 2) * 64;
    int wn = (warp & 3) * 32;

    uint32_t wBase = (uint32_t)__cvta_generic_to_shared(sm.Ws);
    const __half* gW = WT + bC * 128 * DD;
#pragma unroll
    for (int i = 0; i < 16; i++) {
        int ch = tid + i * 256;
        int row = ch >> 5;
        int ko = (ch & 31) * 8;
        CP16(wBase + (row * WSTR + ko) * 2, gW + row * DD + ko);
    }
    CP_COMMIT();

    if (FILL) {
        const int per = (NE + PG - 1) / PG;
        int e0 = cid * per;
        int e1 = e0 + per; if (e1 > NE) e1 = NE;
        for (int e = e0 + tid; e < e1; e += 256) {
            int dst = edge[NE + e];
            int p = atomicAdd(&g_CPOS[dst], 1);
            g_CSRC[p] = edge[e];
        }
    }

    asm volatile("cp.async.wait_group 0;");
    __syncthreads();

    int lrow = lane & 7;
    int sel = lane >> 3;
    int aRow = lrow + ((sel & 1) << 3);
    int aKof = (sel & 2) ? 8 : 0;
    int bRow = lrow + ((sel >> 1) << 3);
    int bKof = (sel & 1) ? 8 : 0;

    uint32_t sA0 = (uint32_t)__cvta_generic_to_shared(&sm.As[0][0]);
    const uint32_t STG_B = 128 * ASTR * 2;
    int mrow = tid >> 1;
    int kh = (tid & 1) * 16;
    uint32_t dOffA = (mrow * ASTR + kh) * 2;

    for (int bR = crow; bR < NRT; bR += 148) {
        int rowA = bR * 128 + mrow;
        int rowAc = rowA < NN ? rowA : NN - 1;
        const __half* gA = g_XH + rowAc * DD + kh;

        float acc[4][4][4];
#pragma unroll
        for (int i = 0; i < 4; i++)
#pragma unroll
            for (int j = 0; j < 4; j++)
#pragma unroll
                for (int q = 0; q < 4; q++) acc[i][j][q] = 0.f;

#pragma unroll
        for (int pt = 0; pt < 2; pt++) {
            uint32_t dA = sA0 + pt * STG_B + dOffA;
            CP16(dA, gA + pt * 32); CP16(dA + 16, gA + pt * 32 + 8);
            CP_COMMIT();
        }

#pragma unroll 1
        for (int it = 0; it < 8; it++) {
            if (it < 7) asm volatile("cp.async.wait_group 1;");
            else        asm volatile("cp.async.wait_group 0;");
            __syncthreads();

            if (it + 2 < 8) {
                int st = (it + 2) % 3;
                uint32_t dA = sA0 + st * STG_B + dOffA;
                CP16(dA, gA + (it + 2) * 32); CP16(dA + 16, gA + (it + 2) * 32 + 8);
                CP_COMMIT();
            }

            uint32_t aBase = sA0 + (it % 3) * STG_B;
#pragma unroll
            for (int kc = 0; kc < 2; kc++) {
                int k0 = it * 32 + kc * 16;
                uint32_t a[4][4], bb[2][4];
#pragma unroll
                for (int ti = 0; ti < 4; ti++) {
                    uint32_t addr = aBase + ((wm + ti * 16 + aRow) * ASTR + kc * 16 + aKof) * 2;
                    LDSM_X4(a[ti][0], a[ti][1], a[ti][2], a[ti][3], addr);
                }
#pragma unroll
                for (int tjp = 0; tjp < 2; tjp++) {
                    uint32_t addr = wBase + ((wn + tjp * 16 + bRow) * WSTR + k0 + bKof) * 2;
                    LDSM_X4(bb[tjp][0], bb[tjp][1], bb[tjp][2], bb[tjp][3], addr);
                }
#pragma unroll
                for (int ti = 0; ti < 4; ti++) {
#pragma unroll
                    for (int tjp = 0; tjp < 2; tjp++) {
                        MMA_F16S(acc[ti][2 * tjp], a[ti][0], a[ti][1], a[ti][2], a[ti][3],
                                 bb[tjp][0], bb[tjp][1]);
                        MMA_F16S(acc[ti][2 * tjp + 1], a[ti][0], a[ti][1], a[ti][2], a[ti][3],
                                 bb[tjp][2], bb[tjp][3]);
                    }
                }
            }
        }
        __syncthreads();

#pragma unroll
        for (int ti = 0; ti < 4; ti++) {
            int row0 = bR * 128 + wm + ti * 16 + r;
            int row1 = row0 + 8;
            float dis0 = (row0 < NN) ? g_DIS[row0] : 0.f;
            float dis1 = (row1 < NN) ? g_DIS[row1] : 0.f;
#pragma unroll
            for (int tj = 0; tj < 4; tj++) {
                int col = bC * 128 + wn + tj * 8 + 2 * c;
                float bx = __ldg(bias + col), by = __ldg(bias + col + 1);
                if (row0 < NN) {
                    __half2 h = __floats2half2_rn((acc[ti][tj][0] + bx) * dis0,
                                                  (acc[ti][tj][1] + by) * dis0);
                    *(__half2*)(g_HSH + row0 * DD + col) = h;
                }
                if (row1 < NN) {
                    __half2 h = __floats2half2_rn((acc[ti][tj][2] + bx) * dis1,
                                                  (acc[ti][tj][3] + by) * dis1);
                    *(__half2*)(g_HSH + row1 * DD + col) = h;
                }
            }
        }
    }
}

// ------- aggregation: warp/node, batched loads (MLP=8) + HADD2 accumulation ----
template <int LAYER1>
__global__ void __launch_bounds__(256) k_agg() {
    if (LAYER1 && blockIdx.x >= WB) {
        int n = (blockIdx.x - WB) * 256 + threadIdx.x;
        if (n < NN) g_DEG[n] = 0;   // reset for next call
        return;
    }
    int w = blockIdx.x * 8 + (threadIdx.x >> 5);
    int lane = threadIdx.x & 31;
    if (w >= NN) return;
    int s = g_ROWPTR[w], e = g_ROWPTR[w + 1];
    const uint4* HS = (const uint4*)g_HSH;
    const __half2 hz = __float2half2_rn(0.f);
    float acc[8];
#pragma unroll
    for (int q = 0; q < 8; q++) acc[q] = 0.f;

    for (int base = s; base < e; base += 32) {
        int cnt = e - base; if (cnt > 32) cnt = 32;
        int mysrc = (lane < cnt) ? g_CSRC[base + lane] : 0;
        int i0 = 0;
        // full groups of 8: batch-issue all loads (MLP=8), then HADD2 + one flush
        for (; i0 + 8 <= cnt; i0 += 8) {
            uint4 v[8];
#pragma unroll
            for (int j = 0; j < 8; j++) {
                int src = __shfl_sync(0xffffffffu, mysrc, i0 + j);
                v[j] = __ldg(HS + src * 32 + lane);
            }
            __half2 ah0 = hz, ah1 = hz, ah2 = hz, ah3 = hz;
#pragma unroll
            for (int j = 0; j < 8; j++) {
                ah0 = __hadd2(ah0, *(__half2*)&v[j].x);
                ah1 = __hadd2(ah1, *(__half2*)&v[j].y);
                ah2 = __hadd2(ah2, *(__half2*)&v[j].z);
                ah3 = __hadd2(ah3, *(__half2*)&v[j].w);
            }
            float2 f0 = __half22float2(ah0), f1 = __half22float2(ah1);
            float2 f2 = __half22float2(ah2), f3 = __half22float2(ah3);
            acc[0] += f0.x; acc[1] += f0.y; acc[2] += f1.x; acc[3] += f1.y;
            acc[4] += f2.x; acc[5] += f2.y; acc[6] += f3.x; acc[7] += f3.y;
        }
        // tail (<8 edges): fp32 path
        for (; i0 < cnt; i0++) {
            int src = __shfl_sync(0xffffffffu, mysrc, i0);
            uint4 v = __ldg(HS + src * 32 + lane);
            float2 f0 = __half22float2(*(__half2*)&v.x);
            float2 f1 = __half22float2(*(__half2*)&v.y);
            float2 f2 = __half22float2(*(__half2*)&v.z);
            float2 f3 = __half22float2(*(__half2*)&v.w);
            acc[0] += f0.x; acc[1] += f0.y; acc[2] += f1.x; acc[3] += f1.y;
            acc[4] += f2.x; acc[5] += f2.y; acc[6] += f3.x; acc[7] += f3.y;
        }
    }
    uint4 sv = __ldg(HS + w * 32 + lane);
    float2 s0 = __half22float2(*(__half2*)&sv.x);
    float2 s1 = __half22float2(*(__half2*)&sv.y);
    float2 s2 = __half22float2(*(__half2*)&sv.z);
    float2 s3 = __half22float2(*(__half2*)&sv.w);
    float dis = g_DIS[w];
    float o[8];
    o[0] = fmaxf(dis * (acc[0] + s0.x), 0.f);
    o[1] = fmaxf(dis * (acc[1] + s0.y), 0.f);
    o[2] = fmaxf(dis * (acc[2] + s1.x), 0.f);
    o[3] = fmaxf(dis * (acc[3] + s1.y), 0.f);
    o[4] = fmaxf(dis * (acc[4] + s2.x), 0.f);
    o[5] = fmaxf(dis * (acc[5] + s2.y), 0.f);
    o[6] = fmaxf(dis * (acc[6] + s3.x), 0.f);
    o[7] = fmaxf(dis * (acc[7] + s3.y), 0.f);
    union { uint4 u; __half2 h2[4]; } pk;
    pk.h2[0] = __floats2half2_rn(o[0], o[1]);
    pk.h2[1] = __floats2half2_rn(o[2], o[3]);
    pk.h2[2] = __floats2half2_rn(o[4], o[5]);
    pk.h2[3] = __floats2half2_rn(o[6], o[7]);
    if (LAYER1) ((uint4*)g_XH)[w * 32 + lane] = pk.u;
    else        ((uint4*)g_UH)[w * 32 + lane] = pk.u;
}

// pool pass 1: 8 node-chunks per graph -> partial sums (fp16 U, fp32 accum)
__global__ void k_pool1() {
    int g = blockIdx.x, ch = blockIdx.y;
    int t = threadIdx.x;
    int s = g_GSTART[g], e = g_GSTART[g + 1];
    int len = e - s;
    int c0 = s + (int)(((long long)len * ch) >> 3);
    int c1 = s + (int)(((long long)len * (ch + 1)) >> 3);
    const uint2* U2 = (const uint2*)g_UH;
    float4 acc = make_float4(0.f, 0.f, 0.f, 0.f);
    for (int n = c0; n < c1; n++) {
        uint2 v = __ldg(U2 + n * 64 + t);
        float2 f0 = __half22float2(*(__half2*)&v.x);
        float2 f1 = __half22float2(*(__half2*)&v.y);
        acc.x += f0.x; acc.y += f0.y; acc.z += f1.x; acc.w += f1.y;
    }
    ((float4*)g_PART)[(ch * NG + g) * 64 + t] = acc;
}

__global__ void k_pool2(float* __restrict__ out) {
    int g = blockIdx.x;
    int t = threadIdx.x;
    const float4* P4 = (const float4*)g_PART;
    float4 acc = make_float4(0.f, 0.f, 0.f, 0.f);
#pragma unroll
    for (int ch = 0; ch < 8; ch++) {
        float4 v = P4[(ch * NG + g) * 64 + t];
        acc.x += v.x; acc.y += v.y; acc.z += v.z; acc.w += v.w;
    }
    ((float4*)out)[g * 64 + t] = acc;
}

// ---------------- launch ------------------------------------------------------

extern "C" void kernel_launch(void* const* d_in, const int* in_sizes, int n_in,
                              void* d_out, int out_size) {
    const int *seq = nullptr, *edge = nullptr, *batch = nullptr;
    const float *emb = nullptr, *W0 = nullptr, *b0 = nullptr, *W1 = nullptr, *b1 = nullptr;
    for (int i = 0; i < n_in; i++) {
        int s = in_sizes[i];
        if (s == NN * 16)            seq  = (const int*)d_in[i];
        else if (s == 2 * NE)        edge = (const int*)d_in[i];
        else if (s == NN)            batch = (const int*)d_in[i];
        else if (s == VOCAB * DD)    emb  = (const float*)d_in[i];
        else if (s == DD * DD) { if (!W0) W0 = (const float*)d_in[i]; else W1 = (const float*)d_in[i]; }
        else if (s == DD)      { if (!b0) b0 = (const float*)d_in[i]; else b1 = (const float*)d_in[i]; }
    }
    float* out = (float*)d_out;

    __half* w0t; cudaGetSymbolAddress((void**)&w0t, g_W0T);
    __half* w1t; cudaGetSymbolAddress((void**)&w1t, g_W1T);

    k_prep<<<VB + 2 + TB + CB, 256>>>(batch, emb, W0, W1, edge);
    k_embed_scan<<<WB + SB, 256>>>(seq);

    // layer 1: persistent GEMM with W0 resident + CSR fill inside
    k_gemm_p<1><<<PG, 256>>>(w0t, b0, edge);
    k_agg<1><<<WB + SB, 256>>>();
    // layer 2
    k_gemm_p<0><<<PG, 256>>>(w1t, b1, nullptr);
    k_agg<0><<<WB, 256>>>();
    // pool
    dim3 pg(NG, 8);
    k_pool1<<<pg, 64>>>();
    k_pool2<<<NG, 64>>>(out);
}

// round 16
// speedup vs baseline: 1.2026x; 1.0502x over previous
#include <cuda_runtime.h>
#include <cuda_fp16.h>
#include <cstdint>

#define NN 50000
#define NG 64
#define DD 256
#define NE 800000
#define VOCAB 100000

#define WB  6250   // embed warp-blocks: NN/8
#define CB  3125   // edge blocks: NE/256
#define SB  196    // ceil(NN/256)
#define VB  12500  // emb-convert blocks: VOCAB/8
#define TB  32     // W-transpose blocks (16 per layer)
#define PG  296    // persistent gemm CTAs (2 per SM x 148)
#define NRT 391    // row tiles: ceil(NN/128)

// ---------------- scratch (device globals: no allocation allowed) -------------
__device__ __half g_EMBH[VOCAB * DD];  // fp16 embedding table (per-call convert)
__device__ __half g_W0T[DD * DD];      // W0 fp16, transposed [n][k]
__device__ __half g_W1T[DD * DD];      // W1 fp16, transposed [n][k]
__device__ __half g_XH[NN * DD];       // layer input fp16
__device__ __half g_HSH[NN * DD];      // h * dis (GEMM out, norm-folded), fp16
__device__ __half g_UH[NN * DD];       // layer2 final node feats (fp16)
__device__ float  g_DIS[NN];           // deg^{-1/2}
__device__ int    g_DEG[NN];           // zero-inited at load; re-zeroed in agg1 tail
__device__ int    g_ROWPTR[NN + 1];
__device__ int    g_CPOS[NN];
__device__ int    g_CSRC[NE];
__device__ int    g_GSTART[NG + 1];
__device__ unsigned long long g_STATE[SB];
__device__ int    g_TICKET;

// ------ prep: emb fp16 ∥ W transpose ∥ scan-state ∥ gstart ∥ out-zero ∥ count --
__global__ void __launch_bounds__(256) k_prep(const int* __restrict__ batch,
                                              const float* __restrict__ emb,
                                              const float* __restrict__ W0,
                                              const float* __restrict__ W1,
                                              const int* __restrict__ edge,
                                              float* __restrict__ out) {
    if (blockIdx.x < VB) {
        int row = blockIdx.x * 8 + (threadIdx.x >> 5);
        int lane = threadIdx.x & 31;
        const float4* src = (const float4*)emb + row * 64;
        float4 v0 = __ldg(src + 2 * lane);
        float4 v1 = __ldg(src + 2 * lane + 1);
        union { uint4 u; __half2 h2[4]; } pk;
        pk.h2[0] = __floats2half2_rn(v0.x, v0.y);
        pk.h2[1] = __floats2half2_rn(v0.z, v0.w);
        pk.h2[2] = __floats2half2_rn(v1.x, v1.y);
        pk.h2[3] = __floats2half2_rn(v1.z, v1.w);
        ((uint4*)g_EMBH)[row * 32 + lane] = pk.u;
        return;
    }
    int b = blockIdx.x - VB;
    int t = threadIdx.x;
    if (b == 0) {
        if (t < SB) g_STATE[t] = 0ull;
        if (t == 0) g_TICKET = 0;
    } else if (b == 1) {
        if (t <= NG) {
            int lo = 0, hi = NN;
            while (lo < hi) {
                int mid = (lo + hi) >> 1;
                if (__ldg(batch + mid) < t) lo = mid + 1; else hi = mid;
            }
            g_GSTART[t] = lo;
        }
    } else if (b == 2) {
        for (int i = t; i < NG * DD; i += 256) out[i] = 0.f;
    } else if (b < 3 + TB) {
        int b2 = b - 3;
        const float* Ws = (b2 < 16) ? W0 : W1;
        __half* Wd = (b2 < 16) ? g_W0T : g_W1T;
        int kbase = (b2 & 15) * 16;
#pragma unroll
        for (int p = 0; p < 8; p++) {
            int k = kbase + 2 * p;
            float v0 = __ldg(Ws + k * DD + t);
            float v1 = __ldg(Ws + (k + 1) * DD + t);
            *(__half2*)&Wd[t * DD + k] = __floats2half2_rn(v0, v1);
        }
    } else {
        int e = (b - 3 - TB) * 256 + t;
        if (e < NE) atomicAdd(&g_DEG[edge[NE + e]], 1);
    }
}

// ---- scan helpers -------------------------------------------------------------
__device__ __forceinline__ int block_scan_incl(int v, int t) {
    __shared__ int ws[8];
    int x = v;
#pragma unroll
    for (int o = 1; o < 32; o <<= 1) {
        int y = __shfl_up_sync(0xffffffffu, x, o);
        if ((t & 31) >= o) x += y;
    }
    if ((t & 31) == 31) ws[t >> 5] = x;
    __syncthreads();
    if (t < 8) {
        int s = ws[t];
#pragma unroll
        for (int o = 1; o < 8; o <<= 1) {
            int y = __shfl_up_sync(0xffu, s, o);
            if (t >= o) s += y;
        }
        ws[t] = s;
    }
    __syncthreads();
    int offs = (t >= 32) ? ws[(t >> 5) - 1] : 0;
    return x + offs;
}

// fused: embed (fp16 gather, HADD2 accum) ∥ decoupled-lookback scan --------------
__global__ void __launch_bounds__(256) k_embed_scan(const int* __restrict__ seq) {
    if (blockIdx.x < WB) {
        int w = blockIdx.x * 8 + (threadIdx.x >> 5);
        int lane = threadIdx.x & 31;
        if (w >= NN) return;
        int tok = (lane < 16) ? seq[w * 16 + lane] : 0;
        const uint4* E = (const uint4*)g_EMBH;
        float acc[8];
#pragma unroll
        for (int q = 0; q < 8; q++) acc[q] = 0.f;
        const __half2 hz = __float2half2_rn(0.f);
#pragma unroll
        for (int g8 = 0; g8 < 2; g8++) {
            __half2 ah0 = hz, ah1 = hz, ah2 = hz, ah3 = hz;
#pragma unroll
            for (int t = 0; t < 8; t++) {
                int tk = __shfl_sync(0xffffffffu, tok, g8 * 8 + t);
                uint4 v = __ldg(E + tk * 32 + lane);
                ah0 = __hadd2(ah0, *(__half2*)&v.x);
                ah1 = __hadd2(ah1, *(__half2*)&v.y);
                ah2 = __hadd2(ah2, *(__half2*)&v.z);
                ah3 = __hadd2(ah3, *(__half2*)&v.w);
            }
            float2 f0 = __half22float2(ah0), f1 = __half22float2(ah1);
            float2 f2 = __half22float2(ah2), f3 = __half22float2(ah3);
            acc[0] += f0.x; acc[1] += f0.y; acc[2] += f1.x; acc[3] += f1.y;
            acc[4] += f2.x; acc[5] += f2.y; acc[6] += f3.x; acc[7] += f3.y;
        }
        union { uint4 u; __half2 h2[4]; } pk;
        pk.h2[0] = __floats2half2_rn(acc[0], acc[1]);
        pk.h2[1] = __floats2half2_rn(acc[2], acc[3]);
        pk.h2[2] = __floats2half2_rn(acc[4], acc[5]);
        pk.h2[3] = __floats2half2_rn(acc[6], acc[7]);
        ((uint4*)g_XH)[w * 32 + lane] = pk.u;
        return;
    }
    // --- scan role (196 blocks, ticket-ordered decoupled lookback) ---
    __shared__ int s_bid, s_total, s_prefix;
    int t = threadIdx.x;
    if (t == 0) s_bid = atomicAdd(&g_TICKET, 1);
    __syncthreads();
    int bid = s_bid;
    int i = bid * 256 + t;
    int deg = (i < NN) ? g_DEG[i] : 0;
    int incl = block_scan_incl(deg, t);
    if (t == 255) s_total = incl;
    __syncthreads();
    if (t == 0) {
        int total = s_total;
        if (bid == 0) {
            atomicExch(&g_STATE[0], (2ull << 32) | (unsigned)total);
            s_prefix = 0;
        } else {
            atomicExch(&g_STATE[bid], (1ull << 32) | (unsigned)total);
            int pref = 0;
            int p = bid - 1;
            while (p >= 0) {
                unsigned long long st;
                do { st = atomicAdd(&g_STATE[p], 0ull); } while ((st >> 32) == 0ull);
                pref += (int)(st & 0xffffffffull);
                if ((st >> 32) == 2ull) break;
                p--;
            }
            s_prefix = pref;
            atomicExch(&g_STATE[bid], (2ull << 32) | (unsigned)(pref + total));
        }
    }
    __syncthreads();
    int rp = s_prefix + incl - deg;
    if (i < NN) {
        g_ROWPTR[i] = rp;
        g_CPOS[i] = rp;
        g_DIS[i] = rsqrtf((float)deg + 1.0f);
    }
    if (i == 0) g_ROWPTR[NN] = NE;
}

// ---------- persistent FP16 GEMM: W resident in smem, A cp.async 3-stage ------
#define MMA_F16S(d, a0, a1, a2, a3, b0, b1)                                    \
    asm volatile(                                                              \
        "mma.sync.aligned.m16n8k16.row.col.f32.f16.f16.f32 "                   \
        "{%0,%1,%2,%3},{%4,%5,%6,%7},{%8,%9},{%0,%1,%2,%3};"                   \
        : "+f"(d[0]), "+f"(d[1]), "+f"(d[2]), "+f"(d[3])                       \
        : "r"(a0), "r"(a1), "r"(a2), "r"(a3), "r"(b0), "r"(b1))

#define LDSM_X4(r0, r1, r2, r3, addr)                                          \
    asm volatile("ldmatrix.sync.aligned.m8n8.x4.shared.b16 {%0,%1,%2,%3}, [%4];" \
                 : "=r"(r0), "=r"(r1), "=r"(r2), "=r"(r3) : "r"(addr))

#define CP16(saddr, gptr)                                                      \
    asm volatile("cp.async.ca.shared.global [%0], [%1], 16;"                   \
                 :: "r"(saddr), "l"(gptr))
#define CP_COMMIT() asm volatile("cp.async.commit_group;")

#define ASTR 40   // A smem row stride (halves)
#define WSTR 264  // W smem row stride (halves)

struct __align__(16) GemmPSmem {
    __half Ws[128 * WSTR];
    __half As[3][128 * ASTR];
};

template <int FILL>
__global__ void __launch_bounds__(256, 2) k_gemm_p(const __half* __restrict__ WT,
                                                   const float* __restrict__ bias,
                                                   const int* __restrict__ edge) {
    __shared__ GemmPSmem sm;
    int cid = blockIdx.x;
    int bC = cid & 1;
    int crow = cid >> 1;
    int tid = threadIdx.x;
    int warp = tid >> 5, lane = tid & 31;
    int r = lane >> 2, c = lane & 3;
    int wm = (warp >> 2) * 64;
    int wn = (warp & 3) * 32;

    uint32_t wBase = (uint32_t)__cvta_generic_to_shared(sm.Ws);
    const __half* gW = WT + bC * 128 * DD;
#pragma unroll
    for (int i = 0; i < 16; i++) {
        int ch = tid + i * 256;
        int row = ch >> 5;
        int ko = (ch & 31) * 8;
        CP16(wBase + (row * WSTR + ko) * 2, gW + row * DD + ko);
    }
    CP_COMMIT();

    if (FILL) {
        const int per = (NE + PG - 1) / PG;
        int e0 = cid * per;
        int e1 = e0 + per; if (e1 > NE) e1 = NE;
        for (int e = e0 + tid; e < e1; e += 256) {
            int dst = edge[NE + e];
            int p = atomicAdd(&g_CPOS[dst], 1);
            g_CSRC[p] = edge[e];
        }
    }

    asm volatile("cp.async.wait_group 0;");
    __syncthreads();

    int lrow = lane & 7;
    int sel = lane >> 3;
    int aRow = lrow + ((sel & 1) << 3);
    int aKof = (sel & 2) ? 8 : 0;
    int bRow = lrow + ((sel >> 1) << 3);
    int bKof = (sel & 1) ? 8 : 0;

    uint32_t sA0 = (uint32_t)__cvta_generic_to_shared(&sm.As[0][0]);
    const uint32_t STG_B = 128 * ASTR * 2;
    int mrow = tid >> 1;
    int kh = (tid & 1) * 16;
    uint32_t dOffA = (mrow * ASTR + kh) * 2;

    for (int bR = crow; bR < NRT; bR += 148) {
        int rowA = bR * 128 + mrow;
        int rowAc = rowA < NN ? rowA : NN - 1;
        const __half* gA = g_XH + rowAc * DD + kh;

        float acc[4][4][4];
#pragma unroll
        for (int i = 0; i < 4; i++)
#pragma unroll
            for (int j = 0; j < 4; j++)
#pragma unroll
                for (int q = 0; q < 4; q++) acc[i][j][q] = 0.f;

#pragma unroll
        for (int pt = 0; pt < 2; pt++) {
            uint32_t dA = sA0 + pt * STG_B + dOffA;
            CP16(dA, gA + pt * 32); CP16(dA + 16, gA + pt * 32 + 8);
            CP_COMMIT();
        }

#pragma unroll 1
        for (int it = 0; it < 8; it++) {
            if (it < 7) asm volatile("cp.async.wait_group 1;");
            else        asm volatile("cp.async.wait_group 0;");
            __syncthreads();

            if (it + 2 < 8) {
                int st = (it + 2) % 3;
                uint32_t dA = sA0 + st * STG_B + dOffA;
                CP16(dA, gA + (it + 2) * 32); CP16(dA + 16, gA + (it + 2) * 32 + 8);
                CP_COMMIT();
            }

            uint32_t aBase = sA0 + (it % 3) * STG_B;
#pragma unroll
            for (int kc = 0; kc < 2; kc++) {
                int k0 = it * 32 + kc * 16;
                uint32_t a[4][4], bb[2][4];
#pragma unroll
                for (int ti = 0; ti < 4; ti++) {
                    uint32_t addr = aBase + ((wm + ti * 16 + aRow) * ASTR + kc * 16 + aKof) * 2;
                    LDSM_X4(a[ti][0], a[ti][1], a[ti][2], a[ti][3], addr);
                }
#pragma unroll
                for (int tjp = 0; tjp < 2; tjp++) {
                    uint32_t addr = wBase + ((wn + tjp * 16 + bRow) * WSTR + k0 + bKof) * 2;
                    LDSM_X4(bb[tjp][0], bb[tjp][1], bb[tjp][2], bb[tjp][3], addr);
                }
#pragma unroll
                for (int ti = 0; ti < 4; ti++) {
#pragma unroll
                    for (int tjp = 0; tjp < 2; tjp++) {
                        MMA_F16S(acc[ti][2 * tjp], a[ti][0], a[ti][1], a[ti][2], a[ti][3],
                                 bb[tjp][0], bb[tjp][1]);
                        MMA_F16S(acc[ti][2 * tjp + 1], a[ti][0], a[ti][1], a[ti][2], a[ti][3],
                                 bb[tjp][2], bb[tjp][3]);
                    }
                }
            }
        }
        __syncthreads();

#pragma unroll
        for (int ti = 0; ti < 4; ti++) {
            int row0 = bR * 128 + wm + ti * 16 + r;
            int row1 = row0 + 8;
            float dis0 = (row0 < NN) ? g_DIS[row0] : 0.f;
            float dis1 = (row1 < NN) ? g_DIS[row1] : 0.f;
#pragma unroll
            for (int tj = 0; tj < 4; tj++) {
                int col = bC * 128 + wn + tj * 8 + 2 * c;
                float bx = __ldg(bias + col), by = __ldg(bias + col + 1);
                if (row0 < NN) {
                    __half2 h = __floats2half2_rn((acc[ti][tj][0] + bx) * dis0,
                                                  (acc[ti][tj][1] + by) * dis0);
                    *(__half2*)(g_HSH + row0 * DD + col) = h;
                }
                if (row1 < NN) {
                    __half2 h = __floats2half2_rn((acc[ti][tj][2] + bx) * dis1,
                                                  (acc[ti][tj][3] + by) * dis1);
                    *(__half2*)(g_HSH + row1 * DD + col) = h;
                }
            }
        }
    }
}

// ------- aggregation: warp/node, batched loads (MLP=4) + HADD2 accumulation ----
template <int LAYER1>
__global__ void __launch_bounds__(256) k_agg() {
    if (LAYER1 && blockIdx.x >= WB) {
        int n = (blockIdx.x - WB) * 256 + threadIdx.x;
        if (n < NN) g_DEG[n] = 0;   // reset for next call
        return;
    }
    int w = blockIdx.x * 8 + (threadIdx.x >> 5);
    int lane = threadIdx.x & 31;
    if (w >= NN) return;
    int s = g_ROWPTR[w], e = g_ROWPTR[w + 1];
    const uint4* HS = (const uint4*)g_HSH;
    const __half2 hz = __float2half2_rn(0.f);
    float acc[8];
#pragma unroll
    for (int q = 0; q < 8; q++) acc[q] = 0.f;

    for (int base = s; base < e; base += 32) {
        int cnt = e - base; if (cnt > 32) cnt = 32;
        int mysrc = (lane < cnt) ? g_CSRC[base + lane] : 0;
        int i0 = 0;
        // full groups of 4: batch-issue loads (MLP=4), then HADD2 + one flush
        for (; i0 + 4 <= cnt; i0 += 4) {
            uint4 v[4];
#pragma unroll
            for (int j = 0; j < 4; j++) {
                int src = __shfl_sync(0xffffffffu, mysrc, i0 + j);
                v[j] = __ldg(HS + src * 32 + lane);
            }
            __half2 ah0 = hz, ah1 = hz, ah2 = hz, ah3 = hz;
#pragma unroll
            for (int j = 0; j < 4; j++) {
                ah0 = __hadd2(ah0, *(__half2*)&v[j].x);
                ah1 = __hadd2(ah1, *(__half2*)&v[j].y);
                ah2 = __hadd2(ah2, *(__half2*)&v[j].z);
                ah3 = __hadd2(ah3, *(__half2*)&v[j].w);
            }
            float2 f0 = __half22float2(ah0), f1 = __half22float2(ah1);
            float2 f2 = __half22float2(ah2), f3 = __half22float2(ah3);
            acc[0] += f0.x; acc[1] += f0.y; acc[2] += f1.x; acc[3] += f1.y;
            acc[4] += f2.x; acc[5] += f2.y; acc[6] += f3.x; acc[7] += f3.y;
        }
        // tail (<4 edges): fp32 path
        for (; i0 < cnt; i0++) {
            int src = __shfl_sync(0xffffffffu, mysrc, i0);
            uint4 v = __ldg(HS + src * 32 + lane);
            float2 f0 = __half22float2(*(__half2*)&v.x);
            float2 f1 = __half22float2(*(__half2*)&v.y);
            float2 f2 = __half22float2(*(__half2*)&v.z);
            float2 f3 = __half22float2(*(__half2*)&v.w);
            acc[0] += f0.x; acc[1] += f0.y; acc[2] += f1.x; acc[3] += f1.y;
            acc[4] += f2.x; acc[5] += f2.y; acc[6] += f3.x; acc[7] += f3.y;
        }
    }
    uint4 sv = __ldg(HS + w * 32 + lane);
    float2 s0 = __half22float2(*(__half2*)&sv.x);
    float2 s1 = __half22float2(*(__half2*)&sv.y);
    float2 s2 = __half22float2(*(__half2*)&sv.z);
    float2 s3 = __half22float2(*(__half2*)&sv.w);
    float dis = g_DIS[w];
    float o[8];
    o[0] = fmaxf(dis * (acc[0] + s0.x), 0.f);
    o[1] = fmaxf(dis * (acc[1] + s0.y), 0.f);
    o[2] = fmaxf(dis * (acc[2] + s1.x), 0.f);
    o[3] = fmaxf(dis * (acc[3] + s1.y), 0.f);
    o[4] = fmaxf(dis * (acc[4] + s2.x), 0.f);
    o[5] = fmaxf(dis * (acc[5] + s2.y), 0.f);
    o[6] = fmaxf(dis * (acc[6] + s3.x), 0.f);
    o[7] = fmaxf(dis * (acc[7] + s3.y), 0.f);
    union { uint4 u; __half2 h2[4]; } pk;
    pk.h2[0] = __floats2half2_rn(o[0], o[1]);
    pk.h2[1] = __floats2half2_rn(o[2], o[3]);
    pk.h2[2] = __floats2half2_rn(o[4], o[5]);
    pk.h2[3] = __floats2half2_rn(o[6], o[7]);
    if (LAYER1) ((uint4*)g_XH)[w * 32 + lane] = pk.u;
    else        ((uint4*)g_UH)[w * 32 + lane] = pk.u;
}

// pool: 8 node-chunks per graph -> atomic add into out (zeroed in prep)
__global__ void k_pool(float* __restrict__ out) {
    int g = blockIdx.x, ch = blockIdx.y;
    int t = threadIdx.x;   // 64 threads, 4 cols each
    int s = g_GSTART[g], e = g_GSTART[g + 1];
    int len = e - s;
    int c0 = s + (int)(((long long)len * ch) >> 3);
    int c1 = s + (int)(((long long)len * (ch + 1)) >> 3);
    const uint2* U2 = (const uint2*)g_UH;
    float4 acc = make_float4(0.f, 0.f, 0.f, 0.f);
    for (int n = c0; n < c1; n++) {
        uint2 v = __ldg(U2 + n * 64 + t);
        float2 f0 = __half22float2(*(__half2*)&v.x);
        float2 f1 = __half22float2(*(__half2*)&v.y);
        acc.x += f0.x; acc.y += f0.y; acc.z += f1.x; acc.w += f1.y;
    }
    float* dst = out + g * DD + t * 4;
    atomicAdd(dst + 0, acc.x);
    atomicAdd(dst + 1, acc.y);
    atomicAdd(dst + 2, acc.z);
    atomicAdd(dst + 3, acc.w);
}

// ---------------- launch ------------------------------------------------------

extern "C" void kernel_launch(void* const* d_in, const int* in_sizes, int n_in,
                              void* d_out, int out_size) {
    const int *seq = nullptr, *edge = nullptr, *batch = nullptr;
    const float *emb = nullptr, *W0 = nullptr, *b0 = nullptr, *W1 = nullptr, *b1 = nullptr;
    for (int i = 0; i < n_in; i++) {
        int s = in_sizes[i];
        if (s == NN * 16)            seq  = (const int*)d_in[i];
        else if (s == 2 * NE)        edge = (const int*)d_in[i];
        else if (s == NN)            batch = (const int*)d_in[i];
        else if (s == VOCAB * DD)    emb  = (const float*)d_in[i];
        else if (s == DD * DD) { if (!W0) W0 = (const float*)d_in[i]; else W1 = (const float*)d_in[i]; }
        else if (s == DD)      { if (!b0) b0 = (const float*)d_in[i]; else b1 = (const float*)d_in[i]; }
    }
    float* out = (float*)d_out;

    __half* w0t; cudaGetSymbolAddress((void**)&w0t, g_W0T);
    __half* w1t; cudaGetSymbolAddress((void**)&w1t, g_W1T);

    k_prep<<<VB + 3 + TB + CB, 256>>>(batch, emb, W0, W1, edge, out);
    k_embed_scan<<<WB + SB, 256>>>(seq);

    // layer 1: persistent GEMM with W0 resident + CSR fill inside
    k_gemm_p<1><<<PG, 256>>>(w0t, b0, edge);
    k_agg<1><<<WB + SB, 256>>>();
    // layer 2
    k_gemm_p<0><<<PG, 256>>>(w1t, b1, nullptr);
    k_agg<0><<<WB, 256>>>();
    // pool (atomic, single pass)
    dim3 pg(NG, 8);
    k_pool<<<pg, 64>>>(out);
}

// round 17
// speedup vs baseline: 1.2262x; 1.0196x over previous
#include <cuda_runtime.h>
#include <cuda_fp16.h>
#include <cstdint>

#define NN 50000
#define NG 64
#define DD 256
#define NE 800000
#define VOCAB 100000

#define WB  6250   // embed warp-blocks: NN/8
#define CB  3125   // edge blocks: NE/256
#define SB  196    // ceil(NN/256)
#define VB  12500  // emb-convert blocks: VOCAB/8
#define TB  32     // W-transpose blocks (16 per layer)
#define PG  296    // persistent gemm CTAs (2 per SM x 148)
#define NRT 391    // row tiles: ceil(NN/128)

// ---------------- scratch (device globals: no allocation allowed) -------------
__device__ __half g_EMBH[VOCAB * DD];  // fp16 embedding table (per-call convert)
__device__ __half g_W0T[DD * DD];      // W0 fp16, transposed [n][k]
__device__ __half g_W1T[DD * DD];      // W1 fp16, transposed [n][k]
__device__ __half g_XH[NN * DD];       // layer input fp16
__device__ __half g_HSH[NN * DD];      // h * dis (GEMM out, norm-folded), fp16
__device__ __half g_UH[NN * DD];       // layer2 final node feats (fp16)
__device__ float  g_DIS[NN];           // deg^{-1/2}
__device__ int    g_DEG[NN];           // zero-inited at load; re-zeroed in agg1 tail
__device__ int    g_ROWPTR[NN + 1];
__device__ int    g_CPOS[NN];
__device__ int    g_CSRC[NE];
__device__ int    g_GSTART[NG + 1];
__device__ unsigned long long g_STATE[SB];
__device__ int    g_TICKET;

// ------ prep: emb fp16 ∥ W transpose ∥ scan-state ∥ gstart ∥ out-zero ∥ count --
__global__ void __launch_bounds__(256) k_prep(const int* __restrict__ batch,
                                              const float* __restrict__ emb,
                                              const float* __restrict__ W0,
                                              const float* __restrict__ W1,
                                              const int* __restrict__ edge,
                                              float* __restrict__ out) {
    if (blockIdx.x < VB) {
        int row = blockIdx.x * 8 + (threadIdx.x >> 5);
        int lane = threadIdx.x & 31;
        const float4* src = (const float4*)emb + row * 64;
        float4 v0 = __ldg(src + 2 * lane);
        float4 v1 = __ldg(src + 2 * lane + 1);
        union { uint4 u; __half2 h2[4]; } pk;
        pk.h2[0] = __floats2half2_rn(v0.x, v0.y);
        pk.h2[1] = __floats2half2_rn(v0.z, v0.w);
        pk.h2[2] = __floats2half2_rn(v1.x, v1.y);
        pk.h2[3] = __floats2half2_rn(v1.z, v1.w);
        ((uint4*)g_EMBH)[row * 32 + lane] = pk.u;
        return;
    }
    int b = blockIdx.x - VB;
    int t = threadIdx.x;
    if (b == 0) {
        if (t < SB) g_STATE[t] = 0ull;
        if (t == 0) g_TICKET = 0;
    } else if (b == 1) {
        if (t <= NG) {
            int lo = 0, hi = NN;
            while (lo < hi) {
                int mid = (lo + hi) >> 1;
                if (__ldg(batch + mid) < t) lo = mid + 1; else hi = mid;
            }
            g_GSTART[t] = lo;
        }
    } else if (b == 2) {
        for (int i = t; i < NG * DD; i += 256) out[i] = 0.f;
    } else if (b < 3 + TB) {
        int b2 = b - 3;
        const float* Ws = (b2 < 16) ? W0 : W1;
        __half* Wd = (b2 < 16) ? g_W0T : g_W1T;
        int kbase = (b2 & 15) * 16;
#pragma unroll
        for (int p = 0; p < 8; p++) {
            int k = kbase + 2 * p;
            float v0 = __ldg(Ws + k * DD + t);
            float v1 = __ldg(Ws + (k + 1) * DD + t);
            *(__half2*)&Wd[t * DD + k] = __floats2half2_rn(v0, v1);
        }
    } else {
        int e = (b - 3 - TB) * 256 + t;
        if (e < NE) atomicAdd(&g_DEG[edge[NE + e]], 1);
    }
}

// ---- scan helpers -------------------------------------------------------------
__device__ __forceinline__ int block_scan_incl(int v, int t) {
    __shared__ int ws[8];
    int x = v;
#pragma unroll
    for (int o = 1; o < 32; o <<= 1) {
        int y = __shfl_up_sync(0xffffffffu, x, o);
        if ((t & 31) >= o) x += y;
    }
    if ((t & 31) == 31) ws[t >> 5] = x;
    __syncthreads();
    if (t < 8) {
        int s = ws[t];
#pragma unroll
        for (int o = 1; o < 8; o <<= 1) {
            int y = __shfl_up_sync(0xffu, s, o);
            if (t >= o) s += y;
        }
        ws[t] = s;
    }
    __syncthreads();
    int offs = (t >= 32) ? ws[(t >> 5) - 1] : 0;
    return x + offs;
}

// fused: embed (fp16 gather, HADD2 accum) ∥ decoupled-lookback scan --------------
__global__ void __launch_bounds__(256) k_embed_scan(const int* __restrict__ seq) {
    if (blockIdx.x < WB) {
        int w = blockIdx.x * 8 + (threadIdx.x >> 5);
        int lane = threadIdx.x & 31;
        if (w >= NN) return;
        int tok = (lane < 16) ? seq[w * 16 + lane] : 0;
        const uint4* E = (const uint4*)g_EMBH;
        float acc[8];
#pragma unroll
        for (int q = 0; q < 8; q++) acc[q] = 0.f;
        const __half2 hz = __float2half2_rn(0.f);
#pragma unroll
        for (int g8 = 0; g8 < 2; g8++) {
            __half2 ah0 = hz, ah1 = hz, ah2 = hz, ah3 = hz;
#pragma unroll
            for (int t = 0; t < 8; t++) {
                int tk = __shfl_sync(0xffffffffu, tok, g8 * 8 + t);
                uint4 v = __ldg(E + tk * 32 + lane);
                ah0 = __hadd2(ah0, *(__half2*)&v.x);
                ah1 = __hadd2(ah1, *(__half2*)&v.y);
                ah2 = __hadd2(ah2, *(__half2*)&v.z);
                ah3 = __hadd2(ah3, *(__half2*)&v.w);
            }
            float2 f0 = __half22float2(ah0), f1 = __half22float2(ah1);
            float2 f2 = __half22float2(ah2), f3 = __half22float2(ah3);
            acc[0] += f0.x; acc[1] += f0.y; acc[2] += f1.x; acc[3] += f1.y;
            acc[4] += f2.x; acc[5] += f2.y; acc[6] += f3.x; acc[7] += f3.y;
        }
        union { uint4 u; __half2 h2[4]; } pk;
        pk.h2[0] = __floats2half2_rn(acc[0], acc[1]);
        pk.h2[1] = __floats2half2_rn(acc[2], acc[3]);
        pk.h2[2] = __floats2half2_rn(acc[4], acc[5]);
        pk.h2[3] = __floats2half2_rn(acc[6], acc[7]);
        ((uint4*)g_XH)[w * 32 + lane] = pk.u;
        return;
    }
    // --- scan role (196 blocks, ticket-ordered decoupled lookback) ---
    __shared__ int s_bid, s_total, s_prefix;
    int t = threadIdx.x;
    if (t == 0) s_bid = atomicAdd(&g_TICKET, 1);
    __syncthreads();
    int bid = s_bid;
    int i = bid * 256 + t;
    int deg = (i < NN) ? g_DEG[i] : 0;
    int incl = block_scan_incl(deg, t);
    if (t == 255) s_total = incl;
    __syncthreads();
    if (t == 0) {
        int total = s_total;
        if (bid == 0) {
            atomicExch(&g_STATE[0], (2ull << 32) | (unsigned)total);
            s_prefix = 0;
        } else {
            atomicExch(&g_STATE[bid], (1ull << 32) | (unsigned)total);
            int pref = 0;
            int p = bid - 1;
            while (p >= 0) {
                unsigned long long st;
                do { st = atomicAdd(&g_STATE[p], 0ull); } while ((st >> 32) == 0ull);
                pref += (int)(st & 0xffffffffull);
                if ((st >> 32) == 2ull) break;
                p--;
            }
            s_prefix = pref;
            atomicExch(&g_STATE[bid], (2ull << 32) | (unsigned)(pref + total));
        }
    }
    __syncthreads();
    int rp = s_prefix + incl - deg;
    if (i < NN) {
        g_ROWPTR[i] = rp;
        g_CPOS[i] = rp;
        g_DIS[i] = rsqrtf((float)deg + 1.0f);
    }
    if (i == 0) g_ROWPTR[NN] = NE;
}

// ---- persistent FP16 GEMM: W resident, A cp.async 2-stage, BK=64 --------------
#define MMA_F16S(d, a0, a1, a2, a3, b0, b1)                                    \
    asm volatile(                                                              \
        "mma.sync.aligned.m16n8k16.row.col.f32.f16.f16.f32 "                   \
        "{%0,%1,%2,%3},{%4,%5,%6,%7},{%8,%9},{%0,%1,%2,%3};"                   \
        : "+f"(d[0]), "+f"(d[1]), "+f"(d[2]), "+f"(d[3])                       \
        : "r"(a0), "r"(a1), "r"(a2), "r"(a3), "r"(b0), "r"(b1))

#define LDSM_X4(r0, r1, r2, r3, addr)                                          \
    asm volatile("ldmatrix.sync.aligned.m8n8.x4.shared.b16 {%0,%1,%2,%3}, [%4];" \
                 : "=r"(r0), "=r"(r1), "=r"(r2), "=r"(r3) : "r"(addr))

#define CP16(saddr, gptr)                                                      \
    asm volatile("cp.async.ca.shared.global [%0], [%1], 16;"                   \
                 :: "r"(saddr), "l"(gptr))
#define CP_COMMIT() asm volatile("cp.async.commit_group;")

#define ASTR 72   // A smem row stride (halves), BK=64 + 8 pad; 144B (16B-mult)
#define WSTR 264  // W smem row stride (halves)

struct __align__(16) GemmPSmem {
    __half Ws[128 * WSTR];     // 67584 B
    __half As[2][128 * ASTR];  // 2 x 18432 B
};

template <int FILL>
__global__ void __launch_bounds__(256, 2) k_gemm_p(const __half* __restrict__ WT,
                                                   const float* __restrict__ bias,
                                                   const int* __restrict__ edge) {
    __shared__ GemmPSmem sm;
    int cid = blockIdx.x;
    int bC = cid & 1;
    int crow = cid >> 1;
    int tid = threadIdx.x;
    int warp = tid >> 5, lane = tid & 31;
    int r = lane >> 2, c = lane & 3;
    int wm = (warp >> 2) * 64;
    int wn = (warp & 3) * 32;

    uint32_t wBase = (uint32_t)__cvta_generic_to_shared(sm.Ws);
    const __half* gW = WT + bC * 128 * DD;
#pragma unroll
    for (int i = 0; i < 16; i++) {
        int ch = tid + i * 256;
        int row = ch >> 5;
        int ko = (ch & 31) * 8;
        CP16(wBase + (row * WSTR + ko) * 2, gW + row * DD + ko);
    }
    CP_COMMIT();

    if (FILL) {
        const int per = (NE + PG - 1) / PG;
        int e0 = cid * per;
        int e1 = e0 + per; if (e1 > NE) e1 = NE;
        for (int e = e0 + tid; e < e1; e += 256) {
            int dst = edge[NE + e];
            int p = atomicAdd(&g_CPOS[dst], 1);
            g_CSRC[p] = edge[e];
        }
    }

    asm volatile("cp.async.wait_group 0;");
    __syncthreads();

    int lrow = lane & 7;
    int sel = lane >> 3;
    int aRow = lrow + ((sel & 1) << 3);
    int aKof = (sel & 2) ? 8 : 0;
    int bRow = lrow + ((sel >> 1) << 3);
    int bKof = (sel & 1) ? 8 : 0;

    uint32_t sA0 = (uint32_t)__cvta_generic_to_shared(&sm.As[0][0]);
    const uint32_t STG_B = 128 * ASTR * 2;
    // A-load chunk mapping: 4 chunks/thread, chunk c -> row=c>>3, kc=(c&7)*8
    int arow0 = tid >> 3;                 // rows for chunks i*32 + ...
    int akc0 = (tid & 7) * 8;

    for (int bR = crow; bR < NRT; bR += 148) {
        float acc[4][4][4];
#pragma unroll
        for (int i = 0; i < 4; i++)
#pragma unroll
            for (int j = 0; j < 4; j++)
#pragma unroll
                for (int q = 0; q < 4; q++) acc[i][j][q] = 0.f;

        // prologue: stage 0 = k-window 0
#pragma unroll
        for (int i = 0; i < 4; i++) {
            int row = arow0 + i * 32;
            int grow = bR * 128 + row; if (grow >= NN) grow = NN - 1;
            CP16(sA0 + (row * ASTR + akc0) * 2, g_XH + grow * DD + akc0);
        }
        CP_COMMIT();

#pragma unroll 1
        for (int it = 0; it < 4; it++) {
            asm volatile("cp.async.wait_group 0;");
            __syncthreads();

            if (it + 1 < 4) {
                int st = (it + 1) & 1;
                int kwin = (it + 1) * 64;
#pragma unroll
                for (int i = 0; i < 4; i++) {
                    int row = arow0 + i * 32;
                    int grow = bR * 128 + row; if (grow >= NN) grow = NN - 1;
                    CP16(sA0 + st * STG_B + (row * ASTR + akc0) * 2,
                         g_XH + grow * DD + kwin + akc0);
                }
                CP_COMMIT();
            }

            uint32_t aBase = sA0 + (it & 1) * STG_B;
#pragma unroll
            for (int kc = 0; kc < 4; kc++) {
                int k0 = it * 64 + kc * 16;
                uint32_t a[4][4], bb[2][4];
#pragma unroll
                for (int ti = 0; ti < 4; ti++) {
                    uint32_t addr = aBase + ((wm + ti * 16 + aRow) * ASTR + kc * 16 + aKof) * 2;
                    LDSM_X4(a[ti][0], a[ti][1], a[ti][2], a[ti][3], addr);
                }
#pragma unroll
                for (int tjp = 0; tjp < 2; tjp++) {
                    uint32_t addr = wBase + ((wn + tjp * 16 + bRow) * WSTR + k0 + bKof) * 2;
                    LDSM_X4(bb[tjp][0], bb[tjp][1], bb[tjp][2], bb[tjp][3], addr);
                }
#pragma unroll
                for (int ti = 0; ti < 4; ti++) {
#pragma unroll
                    for (int tjp = 0; tjp < 2; tjp++) {
                        MMA_F16S(acc[ti][2 * tjp], a[ti][0], a[ti][1], a[ti][2], a[ti][3],
                                 bb[tjp][0], bb[tjp][1]);
                        MMA_F16S(acc[ti][2 * tjp + 1], a[ti][0], a[ti][1], a[ti][2], a[ti][3],
                                 bb[tjp][2], bb[tjp][3]);
                    }
                }
            }
        }
        __syncthreads();  // protect stages before next tile's prologue

        // epilogue: HSH = fp16( (acc + bias) * dis[row] )
#pragma unroll
        for (int ti = 0; ti < 4; ti++) {
            int row0 = bR * 128 + wm + ti * 16 + r;
            int row1 = row0 + 8;
            float dis0 = (row0 < NN) ? g_DIS[row0] : 0.f;
            float dis1 = (row1 < NN) ? g_DIS[row1] : 0.f;
#pragma unroll
            for (int tj = 0; tj < 4; tj++) {
                int col = bC * 128 + wn + tj * 8 + 2 * c;
                float bx = __ldg(bias + col), by = __ldg(bias + col + 1);
                if (row0 < NN) {
                    __half2 h = __floats2half2_rn((acc[ti][tj][0] + bx) * dis0,
                                                  (acc[ti][tj][1] + by) * dis0);
                    *(__half2*)(g_HSH + row0 * DD + col) = h;
                }
                if (row1 < NN) {
                    __half2 h = __floats2half2_rn((acc[ti][tj][2] + bx) * dis1,
                                                  (acc[ti][tj][3] + by) * dis1);
                    *(__half2*)(g_HSH + row1 * DD + col) = h;
                }
            }
        }
    }
}

// ------- aggregation: warp/node, batched loads (MLP=4) + HADD2 accumulation ----
template <int LAYER1>
__global__ void __launch_bounds__(256) k_agg() {
    if (LAYER1 && blockIdx.x >= WB) {
        int n = (blockIdx.x - WB) * 256 + threadIdx.x;
        if (n < NN) g_DEG[n] = 0;   // reset for next call
        return;
    }
    int w = blockIdx.x * 8 + (threadIdx.x >> 5);
    int lane = threadIdx.x & 31;
    if (w >= NN) return;
    int s = g_ROWPTR[w], e = g_ROWPTR[w + 1];
    const uint4* HS = (const uint4*)g_HSH;
    const __half2 hz = __float2half2_rn(0.f);
    uint4 sv = __ldg(HS + w * 32 + lane);   // self-loop row: issue early
    float acc[8];
#pragma unroll
    for (int q = 0; q < 8; q++) acc[q] = 0.f;

    for (int base = s; base < e; base += 32) {
        int cnt = e - base; if (cnt > 32) cnt = 32;
        int mysrc = (lane < cnt) ? g_CSRC[base + lane] : 0;
        int i0 = 0;
        for (; i0 + 4 <= cnt; i0 += 4) {
            uint4 v[4];
#pragma unroll
            for (int j = 0; j < 4; j++) {
                int src = __shfl_sync(0xffffffffu, mysrc, i0 + j);
                v[j] = __ldg(HS + src * 32 + lane);
            }
            __half2 ah0 = hz, ah1 = hz, ah2 = hz, ah3 = hz;
#pragma unroll
            for (int j = 0; j < 4; j++) {
                ah0 = __hadd2(ah0, *(__half2*)&v[j].x);
                ah1 = __hadd2(ah1, *(__half2*)&v[j].y);
                ah2 = __hadd2(ah2, *(__half2*)&v[j].z);
                ah3 = __hadd2(ah3, *(__half2*)&v[j].w);
            }
            float2 f0 = __half22float2(ah0), f1 = __half22float2(ah1);
            float2 f2 = __half22float2(ah2), f3 = __half22float2(ah3);
            acc[0] += f0.x; acc[1] += f0.y; acc[2] += f1.x; acc[3] += f1.y;
            acc[4] += f2.x; acc[5] += f2.y; acc[6] += f3.x; acc[7] += f3.y;
        }
        for (; i0 < cnt; i0++) {
            int src = __shfl_sync(0xffffffffu, mysrc, i0);
            uint4 v = __ldg(HS + src * 32 + lane);
            float2 f0 = __half22float2(*(__half2*)&v.x);
            float2 f1 = __half22float2(*(__half2*)&v.y);
            float2 f2 = __half22float2(*(__half2*)&v.z);
            float2 f3 = __half22float2(*(__half2*)&v.w);
            acc[0] += f0.x; acc[1] += f0.y; acc[2] += f1.x; acc[3] += f1.y;
            acc[4] += f2.x; acc[5] += f2.y; acc[6] += f3.x; acc[7] += f3.y;
        }
    }
    float2 s0 = __half22float2(*(__half2*)&sv.x);
    float2 s1 = __half22float2(*(__half2*)&sv.y);
    float2 s2 = __half22float2(*(__half2*)&sv.z);
    float2 s3 = __half22float2(*(__half2*)&sv.w);
    float dis = g_DIS[w];
    float o[8];
    o[0] = fmaxf(dis * (acc[0] + s0.x), 0.f);
    o[1] = fmaxf(dis * (acc[1] + s0.y), 0.f);
    o[2] = fmaxf(dis * (acc[2] + s1.x), 0.f);
    o[3] = fmaxf(dis * (acc[3] + s1.y), 0.f);
    o[4] = fmaxf(dis * (acc[4] + s2.x), 0.f);
    o[5] = fmaxf(dis * (acc[5] + s2.y), 0.f);
    o[6] = fmaxf(dis * (acc[6] + s3.x), 0.f);
    o[7] = fmaxf(dis * (acc[7] + s3.y), 0.f);
    union { uint4 u; __half2 h2[4]; } pk;
    pk.h2[0] = __floats2half2_rn(o[0], o[1]);
    pk.h2[1] = __floats2half2_rn(o[2], o[3]);
    pk.h2[2] = __floats2half2_rn(o[4], o[5]);
    pk.h2[3] = __floats2half2_rn(o[6], o[7]);
    if (LAYER1) ((uint4*)g_XH)[w * 32 + lane] = pk.u;
    else        ((uint4*)g_UH)[w * 32 + lane] = pk.u;
}

// pool: 8 node-chunks per graph -> atomic add into out (zeroed in prep)
__global__ void k_pool(float* __restrict__ out) {
    int g = blockIdx.x, ch = blockIdx.y;
    int t = threadIdx.x;   // 64 threads, 4 cols each
    int s = g_GSTART[g], e = g_GSTART[g + 1];
    int len = e - s;
    int c0 = s + (int)(((long long)len * ch) >> 3);
    int c1 = s + (int)(((long long)len * (ch + 1)) >> 3);
    const uint2* U2 = (const uint2*)g_UH;
    float4 acc = make_float4(0.f, 0.f, 0.f, 0.f);
    for (int n = c0; n < c1; n++) {
        uint2 v = __ldg(U2 + n * 64 + t);
        float2 f0 = __half22float2(*(__half2*)&v.x);
        float2 f1 = __half22float2(*(__half2*)&v.y);
        acc.x += f0.x; acc.y += f0.y; acc.z += f1.x; acc.w += f1.y;
    }
    float* dst = out + g * DD + t * 4;
    atomicAdd(dst + 0, acc.x);
    atomicAdd(dst + 1, acc.y);
    atomicAdd(dst + 2, acc.z);
    atomicAdd(dst + 3, acc.w);
}

// ---------------- launch ------------------------------------------------------

extern "C" void kernel_launch(void* const* d_in, const int* in_sizes, int n_in,
                              void* d_out, int out_size) {
    const int *seq = nullptr, *edge = nullptr, *batch = nullptr;
    const float *emb = nullptr, *W0 = nullptr, *b0 = nullptr, *W1 = nullptr, *b1 = nullptr;
    for (int i = 0; i < n_in; i++) {
        int s = in_sizes[i];
        if (s == NN * 16)            seq  = (const int*)d_in[i];
        else if (s == 2 * NE)        edge = (const int*)d_in[i];
        else if (s == NN)            batch = (const int*)d_in[i];
        else if (s == VOCAB * DD)    emb  = (const float*)d_in[i];
        else if (s == DD * DD) { if (!W0) W0 = (const float*)d_in[i]; else W1 = (const float*)d_in[i]; }
        else if (s == DD)      { if (!b0) b0 = (const float*)d_in[i]; else b1 = (const float*)d_in[i]; }
    }
    float* out = (float*)d_out;

    __half* w0t; cudaGetSymbolAddress((void**)&w0t, g_W0T);
    __half* w1t; cudaGetSymbolAddress((void**)&w1t, g_W1T);

    k_prep<<<VB + 3 + TB + CB, 256>>>(batch, emb, W0, W1, edge, out);
    k_embed_scan<<<WB + SB, 256>>>(seq);

    // layer 1: persistent GEMM with W0 resident + CSR fill inside
    k_gemm_p<1><<<PG, 256>>>(w0t, b0, edge);
    k_agg<1><<<WB + SB, 256>>>();
    // layer 2
    k_gemm_p<0><<<PG, 256>>>(w1t, b1, nullptr);
    k_agg<0><<<WB, 256>>>();
    // pool (atomic, single pass)
    dim3 pg(NG, 8);
    k_pool<<<pg, 64>>>(out);
}